// round 5
// baseline (speedup 1.0000x reference)
#include <cuda_runtime.h>
#include <cuda_bf16.h>
#include <math.h>
#include <stdint.h>

// ---------------- problem constants ----------------
#define L        1024
#define DMODEL   1024
#define DINNER   2048
#define NH       32
#define HD       64
#define CONVDIM  2176           // DINNER + 2*G*N
#define DINPROJ  4256           // 2*DINNER + 2*G*N + NH
#define DINPROJ_PAD 4352        // 34 * 128
#define OFF_Z    0
#define OFF_XBC  2048
#define OFF_B    2048
#define OFF_DT   4224
#define EPSF     1e-5f

// ---------------- scratch (device globals; no allocs allowed) ----------------
__device__ float g_zx_f[L * DINPROJ];
__device__ float g_zx_b[L * DINPROJ];
__device__ float g_xbc_f[L * CONVDIM];
__device__ float g_xbc_b[L * CONVDIM];
__device__ float g_dt_f[L * NH];
__device__ float g_dt_b[L * NH];
__device__ float g_dA_f[L * NH];
__device__ float g_dA_b[L * NH];
__device__ float g_y_f[L * DINNER];
__device__ float g_y_b[L * DINNER];

// bf16 hi/lo split weights
__device__ __nv_bfloat16 g_winf_hi[DINPROJ_PAD * DMODEL];
__device__ __nv_bfloat16 g_winf_lo[DINPROJ_PAD * DMODEL];
__device__ __nv_bfloat16 g_winb_hi[DINPROJ_PAD * DMODEL];
__device__ __nv_bfloat16 g_winb_lo[DINPROJ_PAD * DMODEL];
__device__ __nv_bfloat16 g_woutf_hi[DMODEL * DINNER];
__device__ __nv_bfloat16 g_woutf_lo[DMODEL * DINNER];
__device__ __nv_bfloat16 g_woutb_hi[DMODEL * DINNER];
__device__ __nv_bfloat16 g_woutb_lo[DMODEL * DINNER];
__device__ __nv_bfloat16 g_wfin_hi[DMODEL * (2 * DMODEL)];
__device__ __nv_bfloat16 g_wfin_lo[DMODEL * (2 * DMODEL)];

// bf16 hi/lo split activations
__device__ __nv_bfloat16 g_uhi[L * DMODEL];
__device__ __nv_bfloat16 g_ulo[L * DMODEL];
__device__ __nv_bfloat16 g_yhi_f[L * DINNER];
__device__ __nv_bfloat16 g_ylo_f[L * DINNER];
__device__ __nv_bfloat16 g_yhi_b[L * DINNER];
__device__ __nv_bfloat16 g_ylo_b[L * DINNER];
__device__ __nv_bfloat16 g_fhi[L * (2 * DMODEL)];
__device__ __nv_bfloat16 g_flo[L * (2 * DMODEL)];

__device__ __forceinline__ float siluf(float x) { return x / (1.f + expf(-x)); }

// ---------------- PTX helpers ----------------
__device__ __forceinline__ uint32_t smem_u32(const void* p) {
    uint32_t a;
    asm("{ .reg .u64 t; cvta.to.shared.u64 t, %1; cvt.u32.u64 %0, t; }" : "=r"(a) : "l"(p));
    return a;
}
__device__ __forceinline__ void cpa16(uint32_t dst, const void* src) {
    asm volatile("cp.async.cg.shared.global [%0], [%1], 16;" :: "r"(dst), "l"(src));
}
#define CP_COMMIT asm volatile("cp.async.commit_group;" ::: "memory")
#define CP_WAIT(n) asm volatile("cp.async.wait_group %0;" :: "n"(n) : "memory")

__device__ __forceinline__ void ldm_x4(uint32_t a[4], uint32_t addr) {
    asm volatile("ldmatrix.sync.aligned.m8n8.x4.shared.b16 {%0,%1,%2,%3}, [%4];"
        : "=r"(a[0]), "=r"(a[1]), "=r"(a[2]), "=r"(a[3]) : "r"(addr));
}
__device__ __forceinline__ void mma_bf16(float c[4], const uint32_t a[4], uint32_t b0, uint32_t b1) {
    asm volatile("mma.sync.aligned.m16n8k16.row.col.f32.bf16.bf16.f32 "
        "{%0,%1,%2,%3}, {%4,%5,%6,%7}, {%8,%9}, {%0,%1,%2,%3};"
        : "+f"(c[0]), "+f"(c[1]), "+f"(c[2]), "+f"(c[3])
        : "r"(a[0]), "r"(a[1]), "r"(a[2]), "r"(a[3]), "r"(b0), "r"(b1));
}
__device__ __forceinline__ uint32_t pack_bf2(__nv_bfloat16 a, __nv_bfloat16 b) {
    __nv_bfloat162 t(a, b);
    return *reinterpret_cast<uint32_t*>(&t);
}

// ---------------- GEMM argument bundle (z-batched f/b) ----------------
struct GemmArgs {
    const __nv_bfloat16 *Ahi0, *Alo0, *Ahi1, *Alo1;
    const __nv_bfloat16 *Whi0, *Wlo0, *Whi1, *Wlo1;
    float *C0, *C1;                 // EPI=0
    __nv_bfloat16 *Ehi, *Elo;       // EPI=1 (silu+split concat buffer, row stride 2048)
    int N, K;
    int flip1;                      // dir-b epilogue row flip
};

// ---------------- HMMA GEMM: C[1024,N] = A[1024,K] * W[N,K]^T ----------------
// 3-term bf16 split: Ahi*Whi + Ahi*Wlo + Alo*Whi, fp32 acc.
// 3-stage cp.async pipeline, one __syncthreads per BK=32 chunk.
// EPI 0: plain fp32 store (optionally row-flipped for z=1).
// EPI 1: silu + bf16 hi/lo split store into Ehi/Elo at column z*1024 (row-flip z=1).
template <int BN, int EPI>
__global__ void __launch_bounds__(256, 2) hmma_gemm(GemmArgs a)
{
    constexpr int STAGE = 16384 + BN * 128;
    constexpr int MT = (BN == 128) ? 4 : 2;
    extern __shared__ __align__(128) char smem[];
    const uint32_t sb = smem_u32(smem);
    const int tid = threadIdx.x;
    const int lane = tid & 31;
    const int wid = tid >> 5;
    const int z = blockIdx.z;
    const int bm = blockIdx.y * 128;
    const int bn = blockIdx.x * BN;
    const int m0w = (BN == 128) ? (wid >> 2) * 64 : (wid >> 1) * 32;
    const int n0w = (BN == 128) ? (wid & 3) * 32 : (wid & 1) * 32;
    const int N = a.N, K = a.K;

    const __nv_bfloat16* Ahi = z ? a.Ahi1 : a.Ahi0;
    const __nv_bfloat16* Alo = z ? a.Alo1 : a.Alo0;
    const __nv_bfloat16* Whi = z ? a.Whi1 : a.Whi0;
    const __nv_bfloat16* Wlo = z ? a.Wlo1 : a.Wlo0;
    const bool flip = z && a.flip1;

    float acc[MT][4][4];
#pragma unroll
    for (int i = 0; i < MT; i++)
#pragma unroll
        for (int j = 0; j < 4; j++)
#pragma unroll
            for (int q = 0; q < 4; q++) acc[i][j][q] = 0.f;

    auto load_stage = [&](int s, int k0) {
        const uint32_t base = sb + s * STAGE;
#pragma unroll
        for (int it = 0; it < 2; it++) {
            const int q = tid + it * 256;
            const int r = q >> 2, c = q & 3;
            const uint32_t sw = r * 64 + ((uint32_t)(c ^ ((r >> 1) & 3)) << 4);
            const size_t go = (size_t)(bm + r) * K + k0 + c * 8;
            cpa16(base + sw, Ahi + go);
            cpa16(base + 8192 + sw, Alo + go);
        }
#pragma unroll
        for (int it = 0; it < BN / 64; it++) {
            const int q = tid + it * 256;
            const int r = q >> 2, c = q & 3;
            const uint32_t sw = r * 64 + ((uint32_t)(c ^ ((r >> 1) & 3)) << 4);
            const size_t go = (size_t)(bn + r) * K + k0 + c * 8;
            cpa16(base + 16384 + sw, Whi + go);
            cpa16(base + 16384 + BN * 64 + sw, Wlo + go);
        }
    };

    const int NC = K >> 5;
    load_stage(0, 0);
    CP_COMMIT;
    load_stage(1, 32);
    CP_COMMIT;

    int cs = 0;
    for (int i = 0; i < NC; i++) {
        if (i + 1 < NC) { CP_WAIT(1); } else { CP_WAIT(0); }
        __syncthreads();
        if (i + 2 < NC) {
            int ps = cs + 2; if (ps >= 3) ps -= 3;
            load_stage(ps, (i + 2) << 5);
            CP_COMMIT;
        }
        const uint32_t base = sb + cs * STAGE;
#pragma unroll
        for (int ks = 0; ks < 2; ks++) {
            const int c0 = ks * 2;
            uint32_t af[MT][4], bh[2][4], bl[2][4];
            // Ahi fragments
#pragma unroll
            for (int ii = 0; ii < MT; ii++) {
                const int row = m0w + ii * 16 + (lane & 15);
                const int ch = c0 + (lane >> 4);
                ldm_x4(af[ii], base + row * 64 + (uint32_t)((ch ^ ((row >> 1) & 3)) << 4));
            }
            // Whi fragments
#pragma unroll
            for (int j = 0; j < 2; j++) {
                const int row = n0w + j * 16 + ((lane >> 4) << 3) + (lane & 7);
                const int ch = c0 + ((lane >> 3) & 1);
                ldm_x4(bh[j], base + 16384 + row * 64 + (uint32_t)((ch ^ ((row >> 1) & 3)) << 4));
            }
            // T1: Ahi * Whi
#pragma unroll
            for (int ii = 0; ii < MT; ii++)
#pragma unroll
                for (int jj = 0; jj < 4; jj++)
                    mma_bf16(acc[ii][jj], af[ii], bh[jj >> 1][(jj & 1) * 2], bh[jj >> 1][(jj & 1) * 2 + 1]);
            // Wlo fragments
#pragma unroll
            for (int j = 0; j < 2; j++) {
                const int row = n0w + j * 16 + ((lane >> 4) << 3) + (lane & 7);
                const int ch = c0 + ((lane >> 3) & 1);
                ldm_x4(bl[j], base + 16384 + BN * 64 + row * 64 + (uint32_t)((ch ^ ((row >> 1) & 3)) << 4));
            }
            // T2: Ahi * Wlo
#pragma unroll
            for (int ii = 0; ii < MT; ii++)
#pragma unroll
                for (int jj = 0; jj < 4; jj++)
                    mma_bf16(acc[ii][jj], af[ii], bl[jj >> 1][(jj & 1) * 2], bl[jj >> 1][(jj & 1) * 2 + 1]);
            // Alo fragments (reuse af regs)
#pragma unroll
            for (int ii = 0; ii < MT; ii++) {
                const int row = m0w + ii * 16 + (lane & 15);
                const int ch = c0 + (lane >> 4);
                ldm_x4(af[ii], base + 8192 + row * 64 + (uint32_t)((ch ^ ((row >> 1) & 3)) << 4));
            }
            // T3: Alo * Whi
#pragma unroll
            for (int ii = 0; ii < MT; ii++)
#pragma unroll
                for (int jj = 0; jj < 4; jj++)
                    mma_bf16(acc[ii][jj], af[ii], bh[jj >> 1][(jj & 1) * 2], bh[jj >> 1][(jj & 1) * 2 + 1]);
        }
        cs++; if (cs >= 3) cs = 0;
    }

    // ---- epilogue ----
    if (EPI == 0) {
        float* C = z ? a.C1 : a.C0;
#pragma unroll
        for (int ii = 0; ii < MT; ii++) {
            const int gr = bm + m0w + ii * 16 + (lane >> 2);
            const int r0 = flip ? (1023 - gr) : gr;
            const int r1 = flip ? (1023 - (gr + 8)) : (gr + 8);
#pragma unroll
            for (int jj = 0; jj < 4; jj++) {
                const int gc = bn + n0w + jj * 8 + (lane & 3) * 2;
                if (gc < N) {
                    *reinterpret_cast<float2*>(&C[(size_t)r0 * N + gc]) = make_float2(acc[ii][jj][0], acc[ii][jj][1]);
                    *reinterpret_cast<float2*>(&C[(size_t)r1 * N + gc]) = make_float2(acc[ii][jj][2], acc[ii][jj][3]);
                }
            }
        }
    } else {
        // silu + bf16 hi/lo split into concat buffer (stride 2048), column offset z*1024
        const int colOff = z * 1024;
#pragma unroll
        for (int ii = 0; ii < MT; ii++) {
            const int gr = bm + m0w + ii * 16 + (lane >> 2);
            const int r0 = flip ? (1023 - gr) : gr;
            const int r1 = flip ? (1023 - (gr + 8)) : (gr + 8);
#pragma unroll
            for (int jj = 0; jj < 4; jj++) {
                const int gc = colOff + bn + n0w + jj * 8 + (lane & 3) * 2;
                float v0 = siluf(acc[ii][jj][0]);
                float v1 = siluf(acc[ii][jj][1]);
                float v2 = siluf(acc[ii][jj][2]);
                float v3 = siluf(acc[ii][jj][3]);
                __nv_bfloat16 h0 = __float2bfloat16(v0), h1 = __float2bfloat16(v1);
                __nv_bfloat16 h2 = __float2bfloat16(v2), h3 = __float2bfloat16(v3);
                __nv_bfloat16 l0 = __float2bfloat16(v0 - __bfloat162float(h0));
                __nv_bfloat16 l1 = __float2bfloat16(v1 - __bfloat162float(h1));
                __nv_bfloat16 l2 = __float2bfloat16(v2 - __bfloat162float(h2));
                __nv_bfloat16 l3 = __float2bfloat16(v3 - __bfloat162float(h3));
                *reinterpret_cast<uint32_t*>(&a.Ehi[(size_t)r0 * 2048 + gc]) = pack_bf2(h0, h1);
                *reinterpret_cast<uint32_t*>(&a.Ehi[(size_t)r1 * 2048 + gc]) = pack_bf2(h2, h3);
                *reinterpret_cast<uint32_t*>(&a.Elo[(size_t)r0 * 2048 + gc]) = pack_bf2(l0, l1);
                *reinterpret_cast<uint32_t*>(&a.Elo[(size_t)r1 * 2048 + gc]) = pack_bf2(l2, l3);
            }
        }
    }
}

// ---------------- W hi/lo split (+ zero pad rows) ----------------
__global__ void w_split_kernel(const float* __restrict__ W,
                               __nv_bfloat16* __restrict__ hi, __nv_bfloat16* __restrict__ lo,
                               int rows, int K)
{
    const int r = blockIdx.y;
    const int c = (blockIdx.x * 256 + threadIdx.x) * 4;
    if (c >= K) return;
    float4 v = make_float4(0.f, 0.f, 0.f, 0.f);
    if (r < rows) v = *reinterpret_cast<const float4*>(&W[(size_t)r * K + c]);
    __nv_bfloat16 hx = __float2bfloat16(v.x), hy = __float2bfloat16(v.y),
                  hz = __float2bfloat16(v.z), hw = __float2bfloat16(v.w);
    __nv_bfloat16 lx = __float2bfloat16(v.x - __bfloat162float(hx));
    __nv_bfloat16 ly = __float2bfloat16(v.y - __bfloat162float(hy));
    __nv_bfloat16 lz = __float2bfloat16(v.z - __bfloat162float(hz));
    __nv_bfloat16 lw = __float2bfloat16(v.w - __bfloat162float(hw));
    *reinterpret_cast<uint2*>(&hi[(size_t)r * K + c]) = make_uint2(pack_bf2(hx, hy), pack_bf2(hz, hw));
    *reinterpret_cast<uint2*>(&lo[(size_t)r * K + c]) = make_uint2(pack_bf2(lx, ly), pack_bf2(lz, lw));
}

// ---------------- u -> hi/lo split ----------------
__global__ void u_split_kernel(const float* __restrict__ u,
                               __nv_bfloat16* __restrict__ hi, __nv_bfloat16* __restrict__ lo)
{
    const int i = (blockIdx.x * 256 + threadIdx.x) * 4;
    float4 v = *reinterpret_cast<const float4*>(&u[i]);
    __nv_bfloat16 hx = __float2bfloat16(v.x), hy = __float2bfloat16(v.y),
                  hz = __float2bfloat16(v.z), hw = __float2bfloat16(v.w);
    __nv_bfloat16 lx = __float2bfloat16(v.x - __bfloat162float(hx));
    __nv_bfloat16 ly = __float2bfloat16(v.y - __bfloat162float(hy));
    __nv_bfloat16 lz = __float2bfloat16(v.z - __bfloat162float(hz));
    __nv_bfloat16 lw = __float2bfloat16(v.w - __bfloat162float(hw));
    *reinterpret_cast<uint2*>(&hi[i]) = make_uint2(pack_bf2(hx, hy), pack_bf2(hz, hw));
    *reinterpret_cast<uint2*>(&lo[i]) = make_uint2(pack_bf2(lx, ly), pack_bf2(lz, lw));
}

// ---------------- depthwise causal conv (width 4) + SiLU, z-batched ----------------
__global__ void conv_silu_kernel(const float* __restrict__ zx0, const float* __restrict__ zx1,
                                 const float* __restrict__ cw0, const float* __restrict__ cw1,
                                 const float* __restrict__ cb0, const float* __restrict__ cb1,
                                 float* __restrict__ out0, float* __restrict__ out1)
{
    const int z = blockIdx.y;
    const float* zx = z ? zx1 : zx0;
    const float* cw = z ? cw1 : cw0;
    const float* cb = z ? cb1 : cb0;
    float* out = z ? out1 : out0;
    const int idx = blockIdx.x * blockDim.x + threadIdx.x;
    if (idx >= L * CONVDIM) return;
    const int t = idx / CONVDIM;
    const int c = idx - t * CONVDIM;
    float acc = cb[c];
#pragma unroll
    for (int k = 0; k < 4; k++) {
        const int tt = t - 3 + k;
        if (tt >= 0)
            acc = fmaf(zx[(size_t)tt * DINPROJ + OFF_XBC + c], cw[c * 4 + k], acc);
    }
    out[(size_t)t * CONVDIM + c] = siluf(acc);
}

// ---------------- dt softplus + dA, z-batched ----------------
__global__ void dt_kernel(const float* __restrict__ zx0, const float* __restrict__ zx1,
                          const float* __restrict__ db0, const float* __restrict__ db1,
                          const float* __restrict__ al0, const float* __restrict__ al1,
                          float* __restrict__ dt0, float* __restrict__ dt1,
                          float* __restrict__ dA0, float* __restrict__ dA1)
{
    const int z = blockIdx.y;
    const float* zx = z ? zx1 : zx0;
    const float* dt_bias = z ? db1 : db0;
    const float* A_log = z ? al1 : al0;
    float* dt_out = z ? dt1 : dt0;
    float* dA_out = z ? dA1 : dA0;
    const int idx = blockIdx.x * blockDim.x + threadIdx.x;
    if (idx >= L * NH) return;
    const int h = idx & (NH - 1);
    const float v = zx[(size_t)(idx >> 5) * DINPROJ + OFF_DT + h] + dt_bias[h];
    const float sp = (v > 20.f) ? v : log1pf(expf(v));
    dt_out[idx] = sp;
    dA_out[idx] = expf(sp * (-expf(A_log[h])));
}

// ---------------- SSM scan, z-batched ----------------
#define SCHUNK 16
__global__ void __launch_bounds__(256) scan_kernel(
    const float* __restrict__ xbc0, const float* __restrict__ xbc1,
    const float* __restrict__ dtp0, const float* __restrict__ dtp1,
    const float* __restrict__ dAp0, const float* __restrict__ dAp1,
    const float* __restrict__ Dp0, const float* __restrict__ Dp1,
    float* __restrict__ y0, float* __restrict__ y1)
{
    const int z = blockIdx.z;
    const float* xbc = z ? xbc1 : xbc0;
    const float* dt = z ? dtp1 : dtp0;
    const float* dA = z ? dAp1 : dAp0;
    const float* Dp = z ? Dp1 : Dp0;
    float* y = z ? y1 : y0;

    const int head = blockIdx.y;
    const int ps   = blockIdx.x;
    const int tid  = threadIdx.x;
    const int pl   = tid >> 3;
    const int n0   = (tid & 7) * 8;
    const float Dh = Dp[head];
    const int xoff = head * HD + ps * 32;

    __shared__ float sB[SCHUNK][64];
    __shared__ float sC[SCHUNK][64];
    __shared__ float sx[SCHUNK][32];
    __shared__ float sdt[SCHUNK];
    __shared__ float sdA[SCHUNK];

    float h[8];
#pragma unroll
    for (int j = 0; j < 8; j++) h[j] = 0.f;

    for (int t0 = 0; t0 < L; t0 += SCHUNK) {
        {
            const int lt = tid >> 4;
            const int lc = (tid & 15) * 4;
            const int t  = t0 + lt;
            *reinterpret_cast<float4*>(&sB[lt][lc]) =
                *reinterpret_cast<const float4*>(&xbc[(size_t)t * CONVDIM + OFF_B + lc]);
            *reinterpret_cast<float4*>(&sC[lt][lc]) =
                *reinterpret_cast<const float4*>(&xbc[(size_t)t * CONVDIM + OFF_B + 64 + lc]);
            if (lc < 32)
                *reinterpret_cast<float4*>(&sx[lt][lc]) =
                    *reinterpret_cast<const float4*>(&xbc[(size_t)t * CONVDIM + xoff + lc]);
            if (tid < SCHUNK) {
                sdt[tid] = dt[(size_t)(t0 + tid) * NH + head];
                sdA[tid] = dA[(size_t)(t0 + tid) * NH + head];
            }
        }
        __syncthreads();

        for (int tt = 0; tt < SCHUNK; tt++) {
            const float dtv = sdt[tt];
            const float dAv = sdA[tt];
            const float xp  = sx[tt][pl];
            const float dtx = dtv * xp;
            float b[8], c[8];
            *reinterpret_cast<float4*>(b)     = *reinterpret_cast<const float4*>(&sB[tt][n0]);
            *reinterpret_cast<float4*>(b + 4) = *reinterpret_cast<const float4*>(&sB[tt][n0 + 4]);
            *reinterpret_cast<float4*>(c)     = *reinterpret_cast<const float4*>(&sC[tt][n0]);
            *reinterpret_cast<float4*>(c + 4) = *reinterpret_cast<const float4*>(&sC[tt][n0 + 4]);
            float acc = 0.f;
#pragma unroll
            for (int j = 0; j < 8; j++) {
                h[j] = fmaf(h[j], dAv, dtx * b[j]);
                acc  = fmaf(h[j], c[j], acc);
            }
            acc += __shfl_down_sync(0xffffffffu, acc, 4, 8);
            acc += __shfl_down_sync(0xffffffffu, acc, 2, 8);
            acc += __shfl_down_sync(0xffffffffu, acc, 1, 8);
            if ((tid & 7) == 0)
                y[(size_t)(t0 + tt) * DINNER + head * HD + ps * 32 + pl] = fmaf(Dh, xp, acc);
        }
        __syncthreads();
    }
}

// ---------------- gate + RMSNorm -> bf16 hi/lo, z-batched ----------------
__global__ void __launch_bounds__(256) gatenorm_kernel(
    const float* __restrict__ zx0, const float* __restrict__ zx1,
    const float* __restrict__ nw0, const float* __restrict__ nw1,
    const float* __restrict__ y0, const float* __restrict__ y1,
    __nv_bfloat16* __restrict__ yh0, __nv_bfloat16* __restrict__ yl0,
    __nv_bfloat16* __restrict__ yh1, __nv_bfloat16* __restrict__ yl1)
{
    const int z = blockIdx.y;
    const float* zx = z ? zx1 : zx0;
    const float* norm_w = z ? nw1 : nw0;
    const float* y = z ? y1 : y0;
    __nv_bfloat16* yhi = z ? yh1 : yh0;
    __nv_bfloat16* ylo = z ? yl1 : yl0;

    const int t = blockIdx.x;
    const int tid = threadIdx.x;
    __shared__ float red[8];

    float vals[8];
    float local = 0.f;
#pragma unroll
    for (int i = 0; i < 8; i++) {
        const int c = tid + i * 256;
        const float zz = zx[(size_t)t * DINPROJ + OFF_Z + c];
        const float yv = y[(size_t)t * DINNER + c];
        const float yg = yv * siluf(zz);
        vals[i] = yg;
        local = fmaf(yg, yg, local);
    }
#pragma unroll
    for (int o = 16; o > 0; o >>= 1)
        local += __shfl_down_sync(0xffffffffu, local, o);
    if ((tid & 31) == 0) red[tid >> 5] = local;
    __syncthreads();
    if (tid < 8) {
        float v = red[tid];
#pragma unroll
        for (int o = 4; o > 0; o >>= 1)
            v += __shfl_down_sync(0xffu, v, o, 8);
        if (tid == 0) red[0] = v;
    }
    __syncthreads();
    const float scale = rsqrtf(red[0] * (1.f / (float)DINNER) + EPSF);
#pragma unroll
    for (int i = 0; i < 8; i++) {
        const int c = tid + i * 256;
        const float v = vals[i] * scale * norm_w[c];
        const __nv_bfloat16 h = __float2bfloat16(v);
        yhi[(size_t)t * DINNER + c] = h;
        ylo[(size_t)t * DINNER + c] = __float2bfloat16(v - __bfloat162float(h));
    }
}

// ---------------- launch ----------------
extern "C" void kernel_launch(void* const* d_in, const int* in_sizes, int n_in,
                              void* d_out, int out_size)
{
    const float* u        = (const float*)d_in[0];
    const float* W_in_f   = (const float*)d_in[1];
    const float* W_in_b   = (const float*)d_in[2];
    const float* conv_w_f = (const float*)d_in[3];
    const float* conv_b_f = (const float*)d_in[4];
    const float* conv_w_b = (const float*)d_in[5];
    const float* conv_b_b = (const float*)d_in[6];
    const float* dtb_f    = (const float*)d_in[7];
    const float* dtb_b    = (const float*)d_in[8];
    const float* Alog_f   = (const float*)d_in[9];
    const float* Alog_b   = (const float*)d_in[10];
    const float* D_f      = (const float*)d_in[11];
    const float* D_b      = (const float*)d_in[12];
    const float* nw_f     = (const float*)d_in[13];
    const float* nw_b     = (const float*)d_in[14];
    const float* W_out_f  = (const float*)d_in[15];
    const float* W_out_b  = (const float*)d_in[16];
    const float* W_out    = (const float*)d_in[17];
    float* out = (float*)d_out;

    float *zx_f, *zx_b, *xbc_f, *xbc_b, *dt_f, *dt_b, *dA_f, *dA_b, *y_f, *y_b;
    cudaGetSymbolAddress((void**)&zx_f,  g_zx_f);
    cudaGetSymbolAddress((void**)&zx_b,  g_zx_b);
    cudaGetSymbolAddress((void**)&xbc_f, g_xbc_f);
    cudaGetSymbolAddress((void**)&xbc_b, g_xbc_b);
    cudaGetSymbolAddress((void**)&dt_f,  g_dt_f);
    cudaGetSymbolAddress((void**)&dt_b,  g_dt_b);
    cudaGetSymbolAddress((void**)&dA_f,  g_dA_f);
    cudaGetSymbolAddress((void**)&dA_b,  g_dA_b);
    cudaGetSymbolAddress((void**)&y_f,   g_y_f);
    cudaGetSymbolAddress((void**)&y_b,   g_y_b);

    __nv_bfloat16 *winf_hi, *winf_lo, *winb_hi, *winb_lo;
    __nv_bfloat16 *woutf_hi, *woutf_lo, *woutb_hi, *woutb_lo, *wfin_hi, *wfin_lo;
    __nv_bfloat16 *uhi, *ulo, *yhi_f, *ylo_f, *yhi_b, *ylo_b, *fhi, *flo;
    cudaGetSymbolAddress((void**)&winf_hi,  g_winf_hi);
    cudaGetSymbolAddress((void**)&winf_lo,  g_winf_lo);
    cudaGetSymbolAddress((void**)&winb_hi,  g_winb_hi);
    cudaGetSymbolAddress((void**)&winb_lo,  g_winb_lo);
    cudaGetSymbolAddress((void**)&woutf_hi, g_woutf_hi);
    cudaGetSymbolAddress((void**)&woutf_lo, g_woutf_lo);
    cudaGetSymbolAddress((void**)&woutb_hi, g_woutb_hi);
    cudaGetSymbolAddress((void**)&woutb_lo, g_woutb_lo);
    cudaGetSymbolAddress((void**)&wfin_hi,  g_wfin_hi);
    cudaGetSymbolAddress((void**)&wfin_lo,  g_wfin_lo);
    cudaGetSymbolAddress((void**)&uhi,   g_uhi);
    cudaGetSymbolAddress((void**)&ulo,   g_ulo);
    cudaGetSymbolAddress((void**)&yhi_f, g_yhi_f);
    cudaGetSymbolAddress((void**)&ylo_f, g_ylo_f);
    cudaGetSymbolAddress((void**)&yhi_b, g_yhi_b);
    cudaGetSymbolAddress((void**)&ylo_b, g_ylo_b);
    cudaGetSymbolAddress((void**)&fhi,   g_fhi);
    cudaGetSymbolAddress((void**)&flo,   g_flo);

    constexpr int SMEM_128 = 3 * (16384 + 128 * 128);
    constexpr int SMEM_64  = 3 * (16384 + 64 * 128);
    cudaFuncSetAttribute(hmma_gemm<128, 0>, cudaFuncAttributeMaxDynamicSharedMemorySize, SMEM_128);
    cudaFuncSetAttribute(hmma_gemm<64, 1>,  cudaFuncAttributeMaxDynamicSharedMemorySize, SMEM_64);
    cudaFuncSetAttribute(hmma_gemm<64, 0>,  cudaFuncAttributeMaxDynamicSharedMemorySize, SMEM_64);

    // idx0: u split
    u_split_kernel<<<L * DMODEL / 1024, 256>>>(u, uhi, ulo);
    // idx1-4: weight splits (in/out, f/b)
    w_split_kernel<<<dim3(1, DINPROJ_PAD), 256>>>(W_in_f, winf_hi, winf_lo, DINPROJ, DMODEL);
    w_split_kernel<<<dim3(1, DINPROJ_PAD), 256>>>(W_in_b, winb_hi, winb_lo, DINPROJ, DMODEL);
    w_split_kernel<<<dim3(2, DMODEL), 256>>>(W_out_f, woutf_hi, woutf_lo, DMODEL, DINNER);
    w_split_kernel<<<dim3(2, DMODEL), 256>>>(W_out_b, woutb_hi, woutb_lo, DMODEL, DINNER);

    // idx5: in_proj GEMM (f+b batched; dir-b output rows flipped == time-reversed input)
    {
        GemmArgs ga = {};
        ga.Ahi0 = uhi; ga.Alo0 = ulo; ga.Ahi1 = uhi; ga.Alo1 = ulo;
        ga.Whi0 = winf_hi; ga.Wlo0 = winf_lo; ga.Whi1 = winb_hi; ga.Wlo1 = winb_lo;
        ga.C0 = zx_f; ga.C1 = zx_b;
        ga.N = DINPROJ; ga.K = DMODEL; ga.flip1 = 1;
        dim3 grid(DINPROJ_PAD / 128, 8, 2);
        hmma_gemm<128, 0><<<grid, 256, SMEM_128>>>(ga);
    }
    // idx6: final-weight split
    w_split_kernel<<<dim3(2, DMODEL), 256>>>(W_out, wfin_hi, wfin_lo, DMODEL, 2 * DMODEL);
    // idx7: conv + silu (f+b)
    conv_silu_kernel<<<dim3((L * CONVDIM + 255) / 256, 2), 256>>>(
        zx_f, zx_b, conv_w_f, conv_w_b, conv_b_f, conv_b_b, xbc_f, xbc_b);
    // idx8: dt / dA (f+b)
    dt_kernel<<<dim3((L * NH + 255) / 256, 2), 256>>>(
        zx_f, zx_b, dtb_f, dtb_b, Alog_f, Alog_b, dt_f, dt_b, dA_f, dA_b);
    // idx9: scan (f+b)
    scan_kernel<<<dim3(2, NH, 2), 256>>>(
        xbc_f, xbc_b, dt_f, dt_b, dA_f, dA_b, D_f, D_b, y_f, y_b);
    // idx10: gate + rmsnorm -> bf16 split (f+b)
    gatenorm_kernel<<<dim3(L, 2), 256>>>(
        zx_f, zx_b, nw_f, nw_b, y_f, y_b, yhi_f, ylo_f, yhi_b, ylo_b);
    // idx11: out_proj GEMM (f+b batched, fused silu+split concat epilogue)
    {
        GemmArgs ga = {};
        ga.Ahi0 = yhi_f; ga.Alo0 = ylo_f; ga.Ahi1 = yhi_b; ga.Alo1 = ylo_b;
        ga.Whi0 = woutf_hi; ga.Wlo0 = woutf_lo; ga.Whi1 = woutb_hi; ga.Wlo1 = woutb_lo;
        ga.Ehi = fhi; ga.Elo = flo;
        ga.N = DMODEL; ga.K = DINNER; ga.flip1 = 1;
        dim3 grid(DMODEL / 64, 8, 2);
        hmma_gemm<64, 1><<<grid, 256, SMEM_64>>>(ga);
    }
    // idx12: final GEMM: silu(concat(o_f, flip(o_b))) @ W_out^T -> out
    {
        GemmArgs ga = {};
        ga.Ahi0 = fhi; ga.Alo0 = flo; ga.Ahi1 = fhi; ga.Alo1 = flo;
        ga.Whi0 = wfin_hi; ga.Wlo0 = wfin_lo; ga.Whi1 = wfin_hi; ga.Wlo1 = wfin_lo;
        ga.C0 = out; ga.C1 = out;
        ga.N = DMODEL; ga.K = 2 * DMODEL; ga.flip1 = 0;
        dim3 grid(DMODEL / 64, 8, 1);
        hmma_gemm<64, 0><<<grid, 256, SMEM_64>>>(ga);
    }
}

// round 7
// speedup vs baseline: 1.4587x; 1.4587x over previous
#include <cuda_runtime.h>
#include <cuda_bf16.h>
#include <math.h>
#include <stdint.h>

// ---------------- problem constants ----------------
#define L        1024
#define DMODEL   1024
#define DINNER   2048
#define NH       32
#define HD       64
#define CONVDIM  2176           // DINNER + 2*G*N
#define DINPROJ  4256           // 2*DINNER + 2*G*N + NH
#define DINPROJ_PAD 4352        // 34 * 128
#define OFF_Z    0
#define OFF_XBC  2048
#define OFF_B    2048
#define OFF_DT   4224
#define EPSF     1e-5f

// ---------------- scratch (device globals; no allocs allowed) ----------------
__device__ float g_zx_f[L * DINPROJ];
__device__ float g_zx_b[L * DINPROJ];
__device__ float g_xbc_f[L * CONVDIM];
__device__ float g_xbc_b[L * CONVDIM];
__device__ float g_dt_f[L * NH];
__device__ float g_dt_b[L * NH];
__device__ float g_dA_f[L * NH];
__device__ float g_dA_b[L * NH];
__device__ float g_y_f[L * DINNER];
__device__ float g_y_b[L * DINNER];

// bf16 hi/lo split weights
__device__ __nv_bfloat16 g_winf_hi[DINPROJ_PAD * DMODEL];
__device__ __nv_bfloat16 g_winf_lo[DINPROJ_PAD * DMODEL];
__device__ __nv_bfloat16 g_winb_hi[DINPROJ_PAD * DMODEL];
__device__ __nv_bfloat16 g_winb_lo[DINPROJ_PAD * DMODEL];
__device__ __nv_bfloat16 g_woutf_hi[DMODEL * DINNER];
__device__ __nv_bfloat16 g_woutf_lo[DMODEL * DINNER];
__device__ __nv_bfloat16 g_woutb_hi[DMODEL * DINNER];
__device__ __nv_bfloat16 g_woutb_lo[DMODEL * DINNER];
__device__ __nv_bfloat16 g_wfin_hi[DMODEL * (2 * DMODEL)];
__device__ __nv_bfloat16 g_wfin_lo[DMODEL * (2 * DMODEL)];

// bf16 hi/lo split activations
__device__ __nv_bfloat16 g_uhi[L * DMODEL];
__device__ __nv_bfloat16 g_ulo[L * DMODEL];
__device__ __nv_bfloat16 g_yhi_f[L * DINNER];
__device__ __nv_bfloat16 g_ylo_f[L * DINNER];
__device__ __nv_bfloat16 g_yhi_b[L * DINNER];
__device__ __nv_bfloat16 g_ylo_b[L * DINNER];
__device__ __nv_bfloat16 g_fhi[L * (2 * DMODEL)];
__device__ __nv_bfloat16 g_flo[L * (2 * DMODEL)];

__device__ __forceinline__ float siluf(float x) { return x / (1.f + expf(-x)); }

// ---------------- PTX helpers ----------------
__device__ __forceinline__ uint32_t smem_u32(const void* p) {
    uint32_t a;
    asm("{ .reg .u64 t; cvta.to.shared.u64 t, %1; cvt.u32.u64 %0, t; }" : "=r"(a) : "l"(p));
    return a;
}
__device__ __forceinline__ void cpa16(uint32_t dst, const void* src) {
    asm volatile("cp.async.cg.shared.global [%0], [%1], 16;" :: "r"(dst), "l"(src));
}
#define CP_COMMIT asm volatile("cp.async.commit_group;" ::: "memory")
#define CP_WAIT(n) asm volatile("cp.async.wait_group %0;" :: "n"(n) : "memory")

__device__ __forceinline__ void ldm_x4(uint32_t a[4], uint32_t addr) {
    asm volatile("ldmatrix.sync.aligned.m8n8.x4.shared.b16 {%0,%1,%2,%3}, [%4];"
        : "=r"(a[0]), "=r"(a[1]), "=r"(a[2]), "=r"(a[3]) : "r"(addr));
}
__device__ __forceinline__ void mma_bf16(float c[4], const uint32_t a[4], uint32_t b0, uint32_t b1) {
    asm volatile("mma.sync.aligned.m16n8k16.row.col.f32.bf16.bf16.f32 "
        "{%0,%1,%2,%3}, {%4,%5,%6,%7}, {%8,%9}, {%0,%1,%2,%3};"
        : "+f"(c[0]), "+f"(c[1]), "+f"(c[2]), "+f"(c[3])
        : "r"(a[0]), "r"(a[1]), "r"(a[2]), "r"(a[3]), "r"(b0), "r"(b1));
}
__device__ __forceinline__ uint32_t pack_bf2(__nv_bfloat16 a, __nv_bfloat16 b) {
    __nv_bfloat162 t(a, b);
    return *reinterpret_cast<uint32_t*>(&t);
}

// ---------------- GEMM argument bundle (z-batched f/b) ----------------
struct GemmArgs {
    const __nv_bfloat16 *Ahi0, *Alo0, *Ahi1, *Alo1;
    const __nv_bfloat16 *Whi0, *Wlo0, *Whi1, *Wlo1;
    float *C0, *C1;                 // EPI=0
    __nv_bfloat16 *Ehi, *Elo;       // EPI=1 (silu+split concat buffer, row stride 2048)
    int N, K;
    int flip1;                      // dir-b epilogue row flip
};

// ================= BN=128 GEMM: 512 threads, 16 warps, warp tile 32x32 =================
// 3-term bf16 split; 3-stage cp.async; no reg spills (~90 regs, launch_bounds(512)).
// Stage layout: Ahi @0(8K), Alo @8192, Whi @16384(8K), Wlo @24576. STAGE=32768.
__global__ void __launch_bounds__(512) hmma_gemm128(GemmArgs a)
{
    constexpr int STAGE = 32768;
    extern __shared__ __align__(128) char smem[];
    const uint32_t sb = smem_u32(smem);
    const int tid = threadIdx.x;
    const int lane = tid & 31;
    const int wid = tid >> 5;             // 0..15
    const int z = blockIdx.z;
    const int bm = blockIdx.y * 128;
    const int bn = blockIdx.x * 128;
    const int m0w = (wid >> 2) * 32;
    const int n0w = (wid & 3) * 32;
    const int N = a.N, K = a.K;

    const __nv_bfloat16* Ahi = z ? a.Ahi1 : a.Ahi0;
    const __nv_bfloat16* Alo = z ? a.Alo1 : a.Alo0;
    const __nv_bfloat16* Whi = z ? a.Whi1 : a.Whi0;
    const __nv_bfloat16* Wlo = z ? a.Wlo1 : a.Wlo0;
    const bool flip = z && a.flip1;

    float acc[2][4][4];
#pragma unroll
    for (int i = 0; i < 2; i++)
#pragma unroll
        for (int j = 0; j < 4; j++)
#pragma unroll
            for (int q = 0; q < 4; q++) acc[i][j][q] = 0.f;

    auto load_stage = [&](int s, int k0) {
        const uint32_t base = sb + s * STAGE;
        const int r = tid >> 2, c = tid & 3;
        const uint32_t sw = r * 64 + ((uint32_t)(c ^ ((r >> 1) & 3)) << 4);
        const size_t goA = (size_t)(bm + r) * K + k0 + c * 8;
        cpa16(base + sw, Ahi + goA);
        cpa16(base + 8192 + sw, Alo + goA);
        const size_t goW = (size_t)(bn + r) * K + k0 + c * 8;
        cpa16(base + 16384 + sw, Whi + goW);
        cpa16(base + 24576 + sw, Wlo + goW);
    };

    const int NC = K >> 5;
    load_stage(0, 0);
    CP_COMMIT;
    load_stage(1, 32);
    CP_COMMIT;

    int cs = 0;
    for (int i = 0; i < NC; i++) {
        if (i + 1 < NC) { CP_WAIT(1); } else { CP_WAIT(0); }
        __syncthreads();
        if (i + 2 < NC) {
            int ps = cs + 2; if (ps >= 3) ps -= 3;
            load_stage(ps, (i + 2) << 5);
            CP_COMMIT;
        }
        const uint32_t base = sb + cs * STAGE;
#pragma unroll
        for (int ks = 0; ks < 2; ks++) {
            const int c0 = ks * 2;
            uint32_t af[2][4], bh[2][4], bl[2][4];
#pragma unroll
            for (int ii = 0; ii < 2; ii++) {
                const int row = m0w + ii * 16 + (lane & 15);
                const int ch = c0 + (lane >> 4);
                ldm_x4(af[ii], base + row * 64 + (uint32_t)((ch ^ ((row >> 1) & 3)) << 4));
            }
#pragma unroll
            for (int j = 0; j < 2; j++) {
                const int row = n0w + j * 16 + ((lane >> 4) << 3) + (lane & 7);
                const int ch = c0 + ((lane >> 3) & 1);
                ldm_x4(bh[j], base + 16384 + row * 64 + (uint32_t)((ch ^ ((row >> 1) & 3)) << 4));
            }
#pragma unroll
            for (int ii = 0; ii < 2; ii++)
#pragma unroll
                for (int jj = 0; jj < 4; jj++)
                    mma_bf16(acc[ii][jj], af[ii], bh[jj >> 1][(jj & 1) * 2], bh[jj >> 1][(jj & 1) * 2 + 1]);
#pragma unroll
            for (int j = 0; j < 2; j++) {
                const int row = n0w + j * 16 + ((lane >> 4) << 3) + (lane & 7);
                const int ch = c0 + ((lane >> 3) & 1);
                ldm_x4(bl[j], base + 24576 + row * 64 + (uint32_t)((ch ^ ((row >> 1) & 3)) << 4));
            }
#pragma unroll
            for (int ii = 0; ii < 2; ii++)
#pragma unroll
                for (int jj = 0; jj < 4; jj++)
                    mma_bf16(acc[ii][jj], af[ii], bl[jj >> 1][(jj & 1) * 2], bl[jj >> 1][(jj & 1) * 2 + 1]);
#pragma unroll
            for (int ii = 0; ii < 2; ii++) {
                const int row = m0w + ii * 16 + (lane & 15);
                const int ch = c0 + (lane >> 4);
                ldm_x4(af[ii], base + 8192 + row * 64 + (uint32_t)((ch ^ ((row >> 1) & 3)) << 4));
            }
#pragma unroll
            for (int ii = 0; ii < 2; ii++)
#pragma unroll
                for (int jj = 0; jj < 4; jj++)
                    mma_bf16(acc[ii][jj], af[ii], bh[jj >> 1][(jj & 1) * 2], bh[jj >> 1][(jj & 1) * 2 + 1]);
        }
        cs++; if (cs >= 3) cs = 0;
    }

    float* C = z ? a.C1 : a.C0;
#pragma unroll
    for (int ii = 0; ii < 2; ii++) {
        const int gr = bm + m0w + ii * 16 + (lane >> 2);
        const int r0 = flip ? (1023 - gr) : gr;
        const int r1 = flip ? (1023 - (gr + 8)) : (gr + 8);
#pragma unroll
        for (int jj = 0; jj < 4; jj++) {
            const int gc = bn + n0w + jj * 8 + (lane & 3) * 2;
            if (gc < N) {
                *reinterpret_cast<float2*>(&C[(size_t)r0 * N + gc]) = make_float2(acc[ii][jj][0], acc[ii][jj][1]);
                *reinterpret_cast<float2*>(&C[(size_t)r1 * N + gc]) = make_float2(acc[ii][jj][2], acc[ii][jj][3]);
            }
        }
    }
}

// ================= BN=64 GEMM: 256 threads, 8 warps, warp tile 32x32 =================
// EPI 0: fp32 store; EPI 1: silu + bf16 hi/lo split into concat buffer (stride 2048).
template <int EPI>
__global__ void __launch_bounds__(256, 2) hmma_gemm64(GemmArgs a)
{
    constexpr int BN = 64;
    constexpr int STAGE = 16384 + BN * 128;   // 24576
    extern __shared__ __align__(128) char smem[];
    const uint32_t sb = smem_u32(smem);
    const int tid = threadIdx.x;
    const int lane = tid & 31;
    const int wid = tid >> 5;
    const int z = blockIdx.z;
    const int bm = blockIdx.y * 128;
    const int bn = blockIdx.x * BN;
    const int m0w = (wid >> 1) * 32;
    const int n0w = (wid & 1) * 32;
    const int N = a.N, K = a.K;

    const __nv_bfloat16* Ahi = z ? a.Ahi1 : a.Ahi0;
    const __nv_bfloat16* Alo = z ? a.Alo1 : a.Alo0;
    const __nv_bfloat16* Whi = z ? a.Whi1 : a.Whi0;
    const __nv_bfloat16* Wlo = z ? a.Wlo1 : a.Wlo0;
    const bool flip = z && a.flip1;

    float acc[2][4][4];
#pragma unroll
    for (int i = 0; i < 2; i++)
#pragma unroll
        for (int j = 0; j < 4; j++)
#pragma unroll
            for (int q = 0; q < 4; q++) acc[i][j][q] = 0.f;

    auto load_stage = [&](int s, int k0) {
        const uint32_t base = sb + s * STAGE;
#pragma unroll
        for (int it = 0; it < 2; it++) {
            const int q = tid + it * 256;
            const int r = q >> 2, c = q & 3;
            const uint32_t sw = r * 64 + ((uint32_t)(c ^ ((r >> 1) & 3)) << 4);
            const size_t go = (size_t)(bm + r) * K + k0 + c * 8;
            cpa16(base + sw, Ahi + go);
            cpa16(base + 8192 + sw, Alo + go);
        }
        {
            const int r = tid >> 2, c = tid & 3;
            const uint32_t sw = r * 64 + ((uint32_t)(c ^ ((r >> 1) & 3)) << 4);
            const size_t go = (size_t)(bn + (r & 63)) * K + k0 + c * 8;
            // first 256 threads cover 64 rows x 4 chunks for Whi and Wlo
            if (r < 64) {
                cpa16(base + 16384 + sw, Whi + go);
                cpa16(base + 16384 + BN * 64 + sw, Wlo + go);
            }
        }
    };

    const int NC = K >> 5;
    load_stage(0, 0);
    CP_COMMIT;
    load_stage(1, 32);
    CP_COMMIT;

    int cs = 0;
    for (int i = 0; i < NC; i++) {
        if (i + 1 < NC) { CP_WAIT(1); } else { CP_WAIT(0); }
        __syncthreads();
        if (i + 2 < NC) {
            int ps = cs + 2; if (ps >= 3) ps -= 3;
            load_stage(ps, (i + 2) << 5);
            CP_COMMIT;
        }
        const uint32_t base = sb + cs * STAGE;
#pragma unroll
        for (int ks = 0; ks < 2; ks++) {
            const int c0 = ks * 2;
            uint32_t af[2][4], bh[2][4], bl[2][4];
#pragma unroll
            for (int ii = 0; ii < 2; ii++) {
                const int row = m0w + ii * 16 + (lane & 15);
                const int ch = c0 + (lane >> 4);
                ldm_x4(af[ii], base + row * 64 + (uint32_t)((ch ^ ((row >> 1) & 3)) << 4));
            }
#pragma unroll
            for (int j = 0; j < 2; j++) {
                const int row = n0w + j * 16 + ((lane >> 4) << 3) + (lane & 7);
                const int ch = c0 + ((lane >> 3) & 1);
                ldm_x4(bh[j], base + 16384 + row * 64 + (uint32_t)((ch ^ ((row >> 1) & 3)) << 4));
            }
#pragma unroll
            for (int ii = 0; ii < 2; ii++)
#pragma unroll
                for (int jj = 0; jj < 4; jj++)
                    mma_bf16(acc[ii][jj], af[ii], bh[jj >> 1][(jj & 1) * 2], bh[jj >> 1][(jj & 1) * 2 + 1]);
#pragma unroll
            for (int j = 0; j < 2; j++) {
                const int row = n0w + j * 16 + ((lane >> 4) << 3) + (lane & 7);
                const int ch = c0 + ((lane >> 3) & 1);
                ldm_x4(bl[j], base + 16384 + BN * 64 + row * 64 + (uint32_t)((ch ^ ((row >> 1) & 3)) << 4));
            }
#pragma unroll
            for (int ii = 0; ii < 2; ii++)
#pragma unroll
                for (int jj = 0; jj < 4; jj++)
                    mma_bf16(acc[ii][jj], af[ii], bl[jj >> 1][(jj & 1) * 2], bl[jj >> 1][(jj & 1) * 2 + 1]);
#pragma unroll
            for (int ii = 0; ii < 2; ii++) {
                const int row = m0w + ii * 16 + (lane & 15);
                const int ch = c0 + (lane >> 4);
                ldm_x4(af[ii], base + 8192 + row * 64 + (uint32_t)((ch ^ ((row >> 1) & 3)) << 4));
            }
#pragma unroll
            for (int ii = 0; ii < 2; ii++)
#pragma unroll
                for (int jj = 0; jj < 4; jj++)
                    mma_bf16(acc[ii][jj], af[ii], bh[jj >> 1][(jj & 1) * 2], bh[jj >> 1][(jj & 1) * 2 + 1]);
        }
        cs++; if (cs >= 3) cs = 0;
    }

    if (EPI == 0) {
        float* C = z ? a.C1 : a.C0;
#pragma unroll
        for (int ii = 0; ii < 2; ii++) {
            const int gr = bm + m0w + ii * 16 + (lane >> 2);
            const int r0 = flip ? (1023 - gr) : gr;
            const int r1 = flip ? (1023 - (gr + 8)) : (gr + 8);
#pragma unroll
            for (int jj = 0; jj < 4; jj++) {
                const int gc = bn + n0w + jj * 8 + (lane & 3) * 2;
                if (gc < N) {
                    *reinterpret_cast<float2*>(&C[(size_t)r0 * N + gc]) = make_float2(acc[ii][jj][0], acc[ii][jj][1]);
                    *reinterpret_cast<float2*>(&C[(size_t)r1 * N + gc]) = make_float2(acc[ii][jj][2], acc[ii][jj][3]);
                }
            }
        }
    } else {
        const int colOff = z * 1024;
#pragma unroll
        for (int ii = 0; ii < 2; ii++) {
            const int gr = bm + m0w + ii * 16 + (lane >> 2);
            const int r0 = flip ? (1023 - gr) : gr;
            const int r1 = flip ? (1023 - (gr + 8)) : (gr + 8);
#pragma unroll
            for (int jj = 0; jj < 4; jj++) {
                const int gc = colOff + bn + n0w + jj * 8 + (lane & 3) * 2;
                float v0 = siluf(acc[ii][jj][0]);
                float v1 = siluf(acc[ii][jj][1]);
                float v2 = siluf(acc[ii][jj][2]);
                float v3 = siluf(acc[ii][jj][3]);
                __nv_bfloat16 h0 = __float2bfloat16(v0), h1 = __float2bfloat16(v1);
                __nv_bfloat16 h2 = __float2bfloat16(v2), h3 = __float2bfloat16(v3);
                __nv_bfloat16 l0 = __float2bfloat16(v0 - __bfloat162float(h0));
                __nv_bfloat16 l1 = __float2bfloat16(v1 - __bfloat162float(h1));
                __nv_bfloat16 l2 = __float2bfloat16(v2 - __bfloat162float(h2));
                __nv_bfloat16 l3 = __float2bfloat16(v3 - __bfloat162float(h3));
                *reinterpret_cast<uint32_t*>(&a.Ehi[(size_t)r0 * 2048 + gc]) = pack_bf2(h0, h1);
                *reinterpret_cast<uint32_t*>(&a.Ehi[(size_t)r1 * 2048 + gc]) = pack_bf2(h2, h3);
                *reinterpret_cast<uint32_t*>(&a.Elo[(size_t)r0 * 2048 + gc]) = pack_bf2(l0, l1);
                *reinterpret_cast<uint32_t*>(&a.Elo[(size_t)r1 * 2048 + gc]) = pack_bf2(l2, l3);
            }
        }
    }
}

// ---------------- W hi/lo split (+ zero pad rows) ----------------
__global__ void w_split_kernel(const float* __restrict__ W,
                               __nv_bfloat16* __restrict__ hi, __nv_bfloat16* __restrict__ lo,
                               int rows, int K)
{
    const int r = blockIdx.y;
    const int c = (blockIdx.x * 256 + threadIdx.x) * 4;
    if (c >= K) return;
    float4 v = make_float4(0.f, 0.f, 0.f, 0.f);
    if (r < rows) v = *reinterpret_cast<const float4*>(&W[(size_t)r * K + c]);
    __nv_bfloat16 hx = __float2bfloat16(v.x), hy = __float2bfloat16(v.y),
                  hz = __float2bfloat16(v.z), hw = __float2bfloat16(v.w);
    __nv_bfloat16 lx = __float2bfloat16(v.x - __bfloat162float(hx));
    __nv_bfloat16 ly = __float2bfloat16(v.y - __bfloat162float(hy));
    __nv_bfloat16 lz = __float2bfloat16(v.z - __bfloat162float(hz));
    __nv_bfloat16 lw = __float2bfloat16(v.w - __bfloat162float(hw));
    *reinterpret_cast<uint2*>(&hi[(size_t)r * K + c]) = make_uint2(pack_bf2(hx, hy), pack_bf2(hz, hw));
    *reinterpret_cast<uint2*>(&lo[(size_t)r * K + c]) = make_uint2(pack_bf2(lx, ly), pack_bf2(lz, lw));
}

// ---------------- u -> hi/lo split ----------------
__global__ void u_split_kernel(const float* __restrict__ u,
                               __nv_bfloat16* __restrict__ hi, __nv_bfloat16* __restrict__ lo)
{
    const int i = (blockIdx.x * 256 + threadIdx.x) * 4;
    float4 v = *reinterpret_cast<const float4*>(&u[i]);
    __nv_bfloat16 hx = __float2bfloat16(v.x), hy = __float2bfloat16(v.y),
                  hz = __float2bfloat16(v.z), hw = __float2bfloat16(v.w);
    __nv_bfloat16 lx = __float2bfloat16(v.x - __bfloat162float(hx));
    __nv_bfloat16 ly = __float2bfloat16(v.y - __bfloat162float(hy));
    __nv_bfloat16 lz = __float2bfloat16(v.z - __bfloat162float(hz));
    __nv_bfloat16 lw = __float2bfloat16(v.w - __bfloat162float(hw));
    *reinterpret_cast<uint2*>(&hi[i]) = make_uint2(pack_bf2(hx, hy), pack_bf2(hz, hw));
    *reinterpret_cast<uint2*>(&lo[i]) = make_uint2(pack_bf2(lx, ly), pack_bf2(lz, lw));
}

// ---------------- depthwise causal conv (width 4) + SiLU, z-batched ----------------
__global__ void conv_silu_kernel(const float* __restrict__ zx0, const float* __restrict__ zx1,
                                 const float* __restrict__ cw0, const float* __restrict__ cw1,
                                 const float* __restrict__ cb0, const float* __restrict__ cb1,
                                 float* __restrict__ out0, float* __restrict__ out1)
{
    const int z = blockIdx.y;
    const float* zx = z ? zx1 : zx0;
    const float* cw = z ? cw1 : cw0;
    const float* cb = z ? cb1 : cb0;
    float* out = z ? out1 : out0;
    const int idx = blockIdx.x * blockDim.x + threadIdx.x;
    if (idx >= L * CONVDIM) return;
    const int t = idx / CONVDIM;
    const int c = idx - t * CONVDIM;
    float acc = cb[c];
#pragma unroll
    for (int k = 0; k < 4; k++) {
        const int tt = t - 3 + k;
        if (tt >= 0)
            acc = fmaf(zx[(size_t)tt * DINPROJ + OFF_XBC + c], cw[c * 4 + k], acc);
    }
    out[(size_t)t * CONVDIM + c] = siluf(acc);
}

// ---------------- dt softplus + dA, z-batched ----------------
__global__ void dt_kernel(const float* __restrict__ zx0, const float* __restrict__ zx1,
                          const float* __restrict__ db0, const float* __restrict__ db1,
                          const float* __restrict__ al0, const float* __restrict__ al1,
                          float* __restrict__ dt0, float* __restrict__ dt1,
                          float* __restrict__ dA0, float* __restrict__ dA1)
{
    const int z = blockIdx.y;
    const float* zx = z ? zx1 : zx0;
    const float* dt_bias = z ? db1 : db0;
    const float* A_log = z ? al1 : al0;
    float* dt_out = z ? dt1 : dt0;
    float* dA_out = z ? dA1 : dA0;
    const int idx = blockIdx.x * blockDim.x + threadIdx.x;
    if (idx >= L * NH) return;
    const int h = idx & (NH - 1);
    const float v = zx[(size_t)(idx >> 5) * DINPROJ + OFF_DT + h] + dt_bias[h];
    const float sp = (v > 20.f) ? v : log1pf(expf(v));
    dt_out[idx] = sp;
    dA_out[idx] = expf(sp * (-expf(A_log[h])));
}

// ---------------- SSM scan, z-batched ----------------
#define SCHUNK 16
__global__ void __launch_bounds__(256) scan_kernel(
    const float* __restrict__ xbc0, const float* __restrict__ xbc1,
    const float* __restrict__ dtp0, const float* __restrict__ dtp1,
    const float* __restrict__ dAp0, const float* __restrict__ dAp1,
    const float* __restrict__ Dp0, const float* __restrict__ Dp1,
    float* __restrict__ y0, float* __restrict__ y1)
{
    const int z = blockIdx.z;
    const float* xbc = z ? xbc1 : xbc0;
    const float* dt = z ? dtp1 : dtp0;
    const float* dA = z ? dAp1 : dAp0;
    const float* Dp = z ? Dp1 : Dp0;
    float* y = z ? y1 : y0;

    const int head = blockIdx.y;
    const int ps   = blockIdx.x;
    const int tid  = threadIdx.x;
    const int pl   = tid >> 3;
    const int n0   = (tid & 7) * 8;
    const float Dh = Dp[head];
    const int xoff = head * HD + ps * 32;

    __shared__ float sB[SCHUNK][64];
    __shared__ float sC[SCHUNK][64];
    __shared__ float sx[SCHUNK][32];
    __shared__ float sdt[SCHUNK];
    __shared__ float sdA[SCHUNK];

    float h[8];
#pragma unroll
    for (int j = 0; j < 8; j++) h[j] = 0.f;

    for (int t0 = 0; t0 < L; t0 += SCHUNK) {
        {
            const int lt = tid >> 4;
            const int lc = (tid & 15) * 4;
            const int t  = t0 + lt;
            *reinterpret_cast<float4*>(&sB[lt][lc]) =
                *reinterpret_cast<const float4*>(&xbc[(size_t)t * CONVDIM + OFF_B + lc]);
            *reinterpret_cast<float4*>(&sC[lt][lc]) =
                *reinterpret_cast<const float4*>(&xbc[(size_t)t * CONVDIM + OFF_B + 64 + lc]);
            if (lc < 32)
                *reinterpret_cast<float4*>(&sx[lt][lc]) =
                    *reinterpret_cast<const float4*>(&xbc[(size_t)t * CONVDIM + xoff + lc]);
            if (tid < SCHUNK) {
                sdt[tid] = dt[(size_t)(t0 + tid) * NH + head];
                sdA[tid] = dA[(size_t)(t0 + tid) * NH + head];
            }
        }
        __syncthreads();

        for (int tt = 0; tt < SCHUNK; tt++) {
            const float dtv = sdt[tt];
            const float dAv = sdA[tt];
            const float xp  = sx[tt][pl];
            const float dtx = dtv * xp;
            float b[8], c[8];
            *reinterpret_cast<float4*>(b)     = *reinterpret_cast<const float4*>(&sB[tt][n0]);
            *reinterpret_cast<float4*>(b + 4) = *reinterpret_cast<const float4*>(&sB[tt][n0 + 4]);
            *reinterpret_cast<float4*>(c)     = *reinterpret_cast<const float4*>(&sC[tt][n0]);
            *reinterpret_cast<float4*>(c + 4) = *reinterpret_cast<const float4*>(&sC[tt][n0 + 4]);
            float acc = 0.f;
#pragma unroll
            for (int j = 0; j < 8; j++) {
                h[j] = fmaf(h[j], dAv, dtx * b[j]);
                acc  = fmaf(h[j], c[j], acc);
            }
            acc += __shfl_down_sync(0xffffffffu, acc, 4, 8);
            acc += __shfl_down_sync(0xffffffffu, acc, 2, 8);
            acc += __shfl_down_sync(0xffffffffu, acc, 1, 8);
            if ((tid & 7) == 0)
                y[(size_t)(t0 + tt) * DINNER + head * HD + ps * 32 + pl] = fmaf(Dh, xp, acc);
        }
        __syncthreads();
    }
}

// ---------------- gate + RMSNorm -> bf16 hi/lo, z-batched ----------------
__global__ void __launch_bounds__(256) gatenorm_kernel(
    const float* __restrict__ zx0, const float* __restrict__ zx1,
    const float* __restrict__ nw0, const float* __restrict__ nw1,
    const float* __restrict__ y0, const float* __restrict__ y1,
    __nv_bfloat16* __restrict__ yh0, __nv_bfloat16* __restrict__ yl0,
    __nv_bfloat16* __restrict__ yh1, __nv_bfloat16* __restrict__ yl1)
{
    const int z = blockIdx.y;
    const float* zx = z ? zx1 : zx0;
    const float* norm_w = z ? nw1 : nw0;
    const float* y = z ? y1 : y0;
    __nv_bfloat16* yhi = z ? yh1 : yh0;
    __nv_bfloat16* ylo = z ? yl1 : yl0;

    const int t = blockIdx.x;
    const int tid = threadIdx.x;
    __shared__ float red[8];

    float vals[8];
    float local = 0.f;
#pragma unroll
    for (int i = 0; i < 8; i++) {
        const int c = tid + i * 256;
        const float zz = zx[(size_t)t * DINPROJ + OFF_Z + c];
        const float yv = y[(size_t)t * DINNER + c];
        const float yg = yv * siluf(zz);
        vals[i] = yg;
        local = fmaf(yg, yg, local);
    }
#pragma unroll
    for (int o = 16; o > 0; o >>= 1)
        local += __shfl_down_sync(0xffffffffu, local, o);
    if ((tid & 31) == 0) red[tid >> 5] = local;
    __syncthreads();
    if (tid < 8) {
        float v = red[tid];
#pragma unroll
        for (int o = 4; o > 0; o >>= 1)
            v += __shfl_down_sync(0xffu, v, o, 8);
        if (tid == 0) red[0] = v;
    }
    __syncthreads();
    const float scale = rsqrtf(red[0] * (1.f / (float)DINNER) + EPSF);
#pragma unroll
    for (int i = 0; i < 8; i++) {
        const int c = tid + i * 256;
        const float v = vals[i] * scale * norm_w[c];
        const __nv_bfloat16 h = __float2bfloat16(v);
        yhi[(size_t)t * DINNER + c] = h;
        ylo[(size_t)t * DINNER + c] = __float2bfloat16(v - __bfloat162float(h));
    }
}

// ---------------- launch ----------------
extern "C" void kernel_launch(void* const* d_in, const int* in_sizes, int n_in,
                              void* d_out, int out_size)
{
    const float* u        = (const float*)d_in[0];
    const float* W_in_f   = (const float*)d_in[1];
    const float* W_in_b   = (const float*)d_in[2];
    const float* conv_w_f = (const float*)d_in[3];
    const float* conv_b_f = (const float*)d_in[4];
    const float* conv_w_b = (const float*)d_in[5];
    const float* conv_b_b = (const float*)d_in[6];
    const float* dtb_f    = (const float*)d_in[7];
    const float* dtb_b    = (const float*)d_in[8];
    const float* Alog_f   = (const float*)d_in[9];
    const float* Alog_b   = (const float*)d_in[10];
    const float* D_f      = (const float*)d_in[11];
    const float* D_b      = (const float*)d_in[12];
    const float* nw_f     = (const float*)d_in[13];
    const float* nw_b     = (const float*)d_in[14];
    const float* W_out_f  = (const float*)d_in[15];
    const float* W_out_b  = (const float*)d_in[16];
    const float* W_out    = (const float*)d_in[17];
    float* out = (float*)d_out;

    float *zx_f, *zx_b, *xbc_f, *xbc_b, *dt_f, *dt_b, *dA_f, *dA_b, *y_f, *y_b;
    cudaGetSymbolAddress((void**)&zx_f,  g_zx_f);
    cudaGetSymbolAddress((void**)&zx_b,  g_zx_b);
    cudaGetSymbolAddress((void**)&xbc_f, g_xbc_f);
    cudaGetSymbolAddress((void**)&xbc_b, g_xbc_b);
    cudaGetSymbolAddress((void**)&dt_f,  g_dt_f);
    cudaGetSymbolAddress((void**)&dt_b,  g_dt_b);
    cudaGetSymbolAddress((void**)&dA_f,  g_dA_f);
    cudaGetSymbolAddress((void**)&dA_b,  g_dA_b);
    cudaGetSymbolAddress((void**)&y_f,   g_y_f);
    cudaGetSymbolAddress((void**)&y_b,   g_y_b);

    __nv_bfloat16 *winf_hi, *winf_lo, *winb_hi, *winb_lo;
    __nv_bfloat16 *woutf_hi, *woutf_lo, *woutb_hi, *woutb_lo, *wfin_hi, *wfin_lo;
    __nv_bfloat16 *uhi, *ulo, *yhi_f, *ylo_f, *yhi_b, *ylo_b, *fhi, *flo;
    cudaGetSymbolAddress((void**)&winf_hi,  g_winf_hi);
    cudaGetSymbolAddress((void**)&winf_lo,  g_winf_lo);
    cudaGetSymbolAddress((void**)&winb_hi,  g_winb_hi);
    cudaGetSymbolAddress((void**)&winb_lo,  g_winb_lo);
    cudaGetSymbolAddress((void**)&woutf_hi, g_woutf_hi);
    cudaGetSymbolAddress((void**)&woutf_lo, g_woutf_lo);
    cudaGetSymbolAddress((void**)&woutb_hi, g_woutb_hi);
    cudaGetSymbolAddress((void**)&woutb_lo, g_woutb_lo);
    cudaGetSymbolAddress((void**)&wfin_hi,  g_wfin_hi);
    cudaGetSymbolAddress((void**)&wfin_lo,  g_wfin_lo);
    cudaGetSymbolAddress((void**)&uhi,   g_uhi);
    cudaGetSymbolAddress((void**)&ulo,   g_ulo);
    cudaGetSymbolAddress((void**)&yhi_f, g_yhi_f);
    cudaGetSymbolAddress((void**)&ylo_f, g_ylo_f);
    cudaGetSymbolAddress((void**)&yhi_b, g_yhi_b);
    cudaGetSymbolAddress((void**)&ylo_b, g_ylo_b);
    cudaGetSymbolAddress((void**)&fhi,   g_fhi);
    cudaGetSymbolAddress((void**)&flo,   g_flo);

    constexpr int SMEM_128 = 3 * 32768;
    constexpr int SMEM_64  = 3 * 24576;
    cudaFuncSetAttribute(hmma_gemm128,    cudaFuncAttributeMaxDynamicSharedMemorySize, SMEM_128);
    cudaFuncSetAttribute(hmma_gemm64<1>,  cudaFuncAttributeMaxDynamicSharedMemorySize, SMEM_64);
    cudaFuncSetAttribute(hmma_gemm64<0>,  cudaFuncAttributeMaxDynamicSharedMemorySize, SMEM_64);

    // launch idx0: u split
    u_split_kernel<<<L * DMODEL / 1024, 256>>>(u, uhi, ulo);
    // idx1-3: splits needed before the big GEMM (+ wfin to fill the slot)
    w_split_kernel<<<dim3(1, DINPROJ_PAD), 256>>>(W_in_f, winf_hi, winf_lo, DINPROJ, DMODEL);
    w_split_kernel<<<dim3(1, DINPROJ_PAD), 256>>>(W_in_b, winb_hi, winb_lo, DINPROJ, DMODEL);
    w_split_kernel<<<dim3(2, DMODEL), 256>>>(W_out, wfin_hi, wfin_lo, DMODEL, 2 * DMODEL);

    // idx4 (ncu capture slot): in_proj GEMM (f+b batched; dir-b rows flipped)
    {
        GemmArgs ga = {};
        ga.Ahi0 = uhi; ga.Alo0 = ulo; ga.Ahi1 = uhi; ga.Alo1 = ulo;
        ga.Whi0 = winf_hi; ga.Wlo0 = winf_lo; ga.Whi1 = winb_hi; ga.Wlo1 = winb_lo;
        ga.C0 = zx_f; ga.C1 = zx_b;
        ga.N = DINPROJ; ga.K = DMODEL; ga.flip1 = 1;
        dim3 grid(DINPROJ_PAD / 128, 8, 2);
        hmma_gemm128<<<grid, 512, SMEM_128>>>(ga);
    }
    // idx5-6: out-proj weight splits
    w_split_kernel<<<dim3(2, DMODEL), 256>>>(W_out_f, woutf_hi, woutf_lo, DMODEL, DINNER);
    w_split_kernel<<<dim3(2, DMODEL), 256>>>(W_out_b, woutb_hi, woutb_lo, DMODEL, DINNER);
    // idx7: conv + silu (f+b)
    conv_silu_kernel<<<dim3((L * CONVDIM + 255) / 256, 2), 256>>>(
        zx_f, zx_b, conv_w_f, conv_w_b, conv_b_f, conv_b_b, xbc_f, xbc_b);
    // idx8: dt / dA (f+b)
    dt_kernel<<<dim3((L * NH + 255) / 256, 2), 256>>>(
        zx_f, zx_b, dtb_f, dtb_b, Alog_f, Alog_b, dt_f, dt_b, dA_f, dA_b);
    // idx9: scan (f+b)
    scan_kernel<<<dim3(2, NH, 2), 256>>>(
        xbc_f, xbc_b, dt_f, dt_b, dA_f, dA_b, D_f, D_b, y_f, y_b);
    // idx10: gate + rmsnorm -> bf16 split (f+b)
    gatenorm_kernel<<<dim3(L, 2), 256>>>(
        zx_f, zx_b, nw_f, nw_b, y_f, y_b, yhi_f, ylo_f, yhi_b, ylo_b);
    // idx11: out_proj GEMM (f+b batched, fused silu+split concat epilogue)
    {
        GemmArgs ga = {};
        ga.Ahi0 = yhi_f; ga.Alo0 = ylo_f; ga.Ahi1 = yhi_b; ga.Alo1 = ylo_b;
        ga.Whi0 = woutf_hi; ga.Wlo0 = woutf_lo; ga.Whi1 = woutb_hi; ga.Wlo1 = woutb_lo;
        ga.Ehi = fhi; ga.Elo = flo;
        ga.N = DMODEL; ga.K = DINNER; ga.flip1 = 1;
        dim3 grid(DMODEL / 64, 8, 2);
        hmma_gemm64<1><<<grid, 256, SMEM_64>>>(ga);
    }
    // idx12: final GEMM: silu(concat(o_f, flip(o_b))) @ W_out^T -> out
    {
        GemmArgs ga = {};
        ga.Ahi0 = fhi; ga.Alo0 = flo; ga.Ahi1 = fhi; ga.Alo1 = flo;
        ga.Whi0 = wfin_hi; ga.Wlo0 = wfin_lo; ga.Whi1 = wfin_hi; ga.Wlo1 = wfin_lo;
        ga.C0 = out; ga.C1 = out;
        ga.N = DMODEL; ga.K = 2 * DMODEL; ga.flip1 = 0;
        dim3 grid(DMODEL / 64, 8, 1);
        hmma_gemm64<0><<<grid, 256, SMEM_64>>>(ga);
    }
}

// round 8
// speedup vs baseline: 2.0713x; 1.4200x over previous
#include <cuda_runtime.h>
#include <cuda_fp16.h>
#include <math.h>
#include <stdint.h>

// ---------------- problem constants ----------------
#define L        1024
#define DMODEL   1024
#define DINNER   2048
#define NH       32
#define HD       64
#define CONVDIM  2176           // DINNER + 2*G*N
#define DINPROJ  4256           // 2*DINNER + 2*G*N + NH
#define DINPROJ_PAD 4352        // 34 * 128
#define OFF_Z    0
#define OFF_XBC  2048
#define OFF_B    2048
#define OFF_DT   4224
#define EPSF     1e-5f

// ---------------- scratch (device globals; no allocs allowed) ----------------
__device__ float g_zx_f[L * DINPROJ];
__device__ float g_zx_b[L * DINPROJ];
__device__ float g_xbc_f[L * CONVDIM];
__device__ float g_xbc_b[L * CONVDIM];
__device__ float g_dt_f[L * NH];
__device__ float g_dt_b[L * NH];
__device__ float g_dA_f[L * NH];
__device__ float g_dA_b[L * NH];
__device__ float g_y_f[L * DINNER];
__device__ float g_y_b[L * DINNER];

// fp16 operands
__device__ __half g_u16[L * DMODEL];
__device__ __half g_win16_f[DINPROJ_PAD * DMODEL];
__device__ __half g_win16_b[DINPROJ_PAD * DMODEL];
__device__ __half g_wout16_f[DMODEL * DINNER];
__device__ __half g_wout16_b[DMODEL * DINNER];
__device__ __half g_wfin16[DMODEL * (2 * DMODEL)];
__device__ __half g_y16_f[L * DINNER];
__device__ __half g_y16_b[L * DINNER];
__device__ __half g_f16[L * (2 * DMODEL)];

__device__ __forceinline__ float siluf(float x) { return x / (1.f + expf(-x)); }

// ---------------- PTX helpers ----------------
__device__ __forceinline__ uint32_t smem_u32(const void* p) {
    uint32_t a;
    asm("{ .reg .u64 t; cvta.to.shared.u64 t, %1; cvt.u32.u64 %0, t; }" : "=r"(a) : "l"(p));
    return a;
}
__device__ __forceinline__ void cpa16(uint32_t dst, const void* src) {
    asm volatile("cp.async.cg.shared.global [%0], [%1], 16;" :: "r"(dst), "l"(src));
}
#define CP_COMMIT asm volatile("cp.async.commit_group;" ::: "memory")
#define CP_WAIT(n) asm volatile("cp.async.wait_group %0;" :: "n"(n) : "memory")

__device__ __forceinline__ void ldm_x4(uint32_t a[4], uint32_t addr) {
    asm volatile("ldmatrix.sync.aligned.m8n8.x4.shared.b16 {%0,%1,%2,%3}, [%4];"
        : "=r"(a[0]), "=r"(a[1]), "=r"(a[2]), "=r"(a[3]) : "r"(addr));
}
__device__ __forceinline__ void mma_f16(float c[4], const uint32_t a[4], uint32_t b0, uint32_t b1) {
    asm volatile("mma.sync.aligned.m16n8k16.row.col.f32.f16.f16.f32 "
        "{%0,%1,%2,%3}, {%4,%5,%6,%7}, {%8,%9}, {%0,%1,%2,%3};"
        : "+f"(c[0]), "+f"(c[1]), "+f"(c[2]), "+f"(c[3])
        : "r"(a[0]), "r"(a[1]), "r"(a[2]), "r"(a[3]), "r"(b0), "r"(b1));
}
__device__ __forceinline__ uint32_t pack_h2(__half a, __half b) {
    __half2 t(a, b);
    return *reinterpret_cast<uint32_t*>(&t);
}

// ---------------- GEMM argument bundle ----------------
struct GArgs {
    const __half *A0, *A1, *W0, *W1;
    float *C0, *C1;        // EPI=0
    __half *E;             // EPI=1 (silu -> f16 concat buffer, row stride 2048)
    int N, K;
    int flip0, flip1;      // epilogue row flips per z
};

// ================= BN=128 GEMM: 512 threads, warp tile 32x32, fp16 single-term =================
// Stage: A[128x32 f16] @0 (8K), W[128x32 f16] @8192. STAGE=16384. 3 stages.
__global__ void __launch_bounds__(512) gemm128(GArgs a)
{
    constexpr int STAGE = 16384;
    extern __shared__ __align__(128) char smem[];
    const uint32_t sb = smem_u32(smem);
    const int tid = threadIdx.x;
    const int lane = tid & 31;
    const int wid = tid >> 5;             // 0..15
    const int z = blockIdx.z;
    const int bm = blockIdx.y * 128;
    const int bn = blockIdx.x * 128;
    const int m0w = (wid >> 2) * 32;
    const int n0w = (wid & 3) * 32;
    const int N = a.N, K = a.K;

    const __half* A = z ? a.A1 : a.A0;
    const __half* W = z ? a.W1 : a.W0;
    const bool flip = z ? (a.flip1 != 0) : (a.flip0 != 0);

    float acc[2][4][4];
#pragma unroll
    for (int i = 0; i < 2; i++)
#pragma unroll
        for (int j = 0; j < 4; j++)
#pragma unroll
            for (int q = 0; q < 4; q++) acc[i][j][q] = 0.f;

    auto load_stage = [&](int s, int k0) {
        const uint32_t base = sb + s * STAGE;
        const int r = tid >> 2, c = tid & 3;
        const uint32_t sw = r * 64 + ((uint32_t)(c ^ ((r >> 1) & 3)) << 4);
        cpa16(base + sw, A + (size_t)(bm + r) * K + k0 + c * 8);
        cpa16(base + 8192 + sw, W + (size_t)(bn + r) * K + k0 + c * 8);
    };

    const int NC = K >> 5;
    load_stage(0, 0);
    CP_COMMIT;
    load_stage(1, 32);
    CP_COMMIT;

    int cs = 0;
    for (int i = 0; i < NC; i++) {
        if (i + 1 < NC) { CP_WAIT(1); } else { CP_WAIT(0); }
        __syncthreads();
        if (i + 2 < NC) {
            int ps = cs + 2; if (ps >= 3) ps -= 3;
            load_stage(ps, (i + 2) << 5);
            CP_COMMIT;
        }
        const uint32_t base = sb + cs * STAGE;
#pragma unroll
        for (int ks = 0; ks < 2; ks++) {
            const int c0 = ks * 2;
            uint32_t af[2][4], bw[2][4];
#pragma unroll
            for (int ii = 0; ii < 2; ii++) {
                const int row = m0w + ii * 16 + (lane & 15);
                const int ch = c0 + (lane >> 4);
                ldm_x4(af[ii], base + row * 64 + (uint32_t)((ch ^ ((row >> 1) & 3)) << 4));
            }
#pragma unroll
            for (int j = 0; j < 2; j++) {
                const int row = n0w + j * 16 + ((lane >> 4) << 3) + (lane & 7);
                const int ch = c0 + ((lane >> 3) & 1);
                ldm_x4(bw[j], base + 8192 + row * 64 + (uint32_t)((ch ^ ((row >> 1) & 3)) << 4));
            }
#pragma unroll
            for (int ii = 0; ii < 2; ii++)
#pragma unroll
                for (int jj = 0; jj < 4; jj++)
                    mma_f16(acc[ii][jj], af[ii], bw[jj >> 1][(jj & 1) * 2], bw[jj >> 1][(jj & 1) * 2 + 1]);
        }
        cs++; if (cs >= 3) cs = 0;
    }

    float* C = z ? a.C1 : a.C0;
#pragma unroll
    for (int ii = 0; ii < 2; ii++) {
        const int gr = bm + m0w + ii * 16 + (lane >> 2);
        const int r0 = flip ? (1023 - gr) : gr;
        const int r1 = flip ? (1023 - (gr + 8)) : (gr + 8);
#pragma unroll
        for (int jj = 0; jj < 4; jj++) {
            const int gc = bn + n0w + jj * 8 + (lane & 3) * 2;
            if (gc < N) {
                *reinterpret_cast<float2*>(&C[(size_t)r0 * N + gc]) = make_float2(acc[ii][jj][0], acc[ii][jj][1]);
                *reinterpret_cast<float2*>(&C[(size_t)r1 * N + gc]) = make_float2(acc[ii][jj][2], acc[ii][jj][3]);
            }
        }
    }
}

// ================= BN=64 GEMM: 256 threads, warp tile 32x32, fp16 single-term =================
// Stage: A[128x32] @0 (8K), W[64x32] @8192 (4K). STAGE=12288. 3 stages.
// EPI 0: fp32 store; EPI 1: silu -> f16 store into concat buffer (stride 2048, colOff z*1024).
template <int EPI>
__global__ void __launch_bounds__(256, 2) gemm64(GArgs a)
{
    constexpr int STAGE = 12288;
    extern __shared__ __align__(128) char smem[];
    const uint32_t sb = smem_u32(smem);
    const int tid = threadIdx.x;
    const int lane = tid & 31;
    const int wid = tid >> 5;
    const int z = blockIdx.z;
    const int bm = blockIdx.y * 128;
    const int bn = blockIdx.x * 64;
    const int m0w = (wid >> 1) * 32;
    const int n0w = (wid & 1) * 32;
    const int N = a.N, K = a.K;

    const __half* A = z ? a.A1 : a.A0;
    const __half* W = z ? a.W1 : a.W0;
    const bool flip = z ? (a.flip1 != 0) : (a.flip0 != 0);

    float acc[2][4][4];
#pragma unroll
    for (int i = 0; i < 2; i++)
#pragma unroll
        for (int j = 0; j < 4; j++)
#pragma unroll
            for (int q = 0; q < 4; q++) acc[i][j][q] = 0.f;

    auto load_stage = [&](int s, int k0) {
        const uint32_t base = sb + s * STAGE;
#pragma unroll
        for (int it = 0; it < 2; it++) {
            const int q = tid + it * 256;
            const int r = q >> 2, c = q & 3;
            const uint32_t sw = r * 64 + ((uint32_t)(c ^ ((r >> 1) & 3)) << 4);
            cpa16(base + sw, A + (size_t)(bm + r) * K + k0 + c * 8);
        }
        {
            const int r = tid >> 2, c = tid & 3;
            if (r < 64) {
                const uint32_t sw = r * 64 + ((uint32_t)(c ^ ((r >> 1) & 3)) << 4);
                cpa16(base + 8192 + sw, W + (size_t)(bn + r) * K + k0 + c * 8);
            }
        }
    };

    const int NC = K >> 5;
    load_stage(0, 0);
    CP_COMMIT;
    load_stage(1, 32);
    CP_COMMIT;

    int cs = 0;
    for (int i = 0; i < NC; i++) {
        if (i + 1 < NC) { CP_WAIT(1); } else { CP_WAIT(0); }
        __syncthreads();
        if (i + 2 < NC) {
            int ps = cs + 2; if (ps >= 3) ps -= 3;
            load_stage(ps, (i + 2) << 5);
            CP_COMMIT;
        }
        const uint32_t base = sb + cs * STAGE;
#pragma unroll
        for (int ks = 0; ks < 2; ks++) {
            const int c0 = ks * 2;
            uint32_t af[2][4], bw[2][4];
#pragma unroll
            for (int ii = 0; ii < 2; ii++) {
                const int row = m0w + ii * 16 + (lane & 15);
                const int ch = c0 + (lane >> 4);
                ldm_x4(af[ii], base + row * 64 + (uint32_t)((ch ^ ((row >> 1) & 3)) << 4));
            }
#pragma unroll
            for (int j = 0; j < 2; j++) {
                const int row = n0w + j * 16 + ((lane >> 4) << 3) + (lane & 7);
                const int ch = c0 + ((lane >> 3) & 1);
                ldm_x4(bw[j], base + 8192 + row * 64 + (uint32_t)((ch ^ ((row >> 1) & 3)) << 4));
            }
#pragma unroll
            for (int ii = 0; ii < 2; ii++)
#pragma unroll
                for (int jj = 0; jj < 4; jj++)
                    mma_f16(acc[ii][jj], af[ii], bw[jj >> 1][(jj & 1) * 2], bw[jj >> 1][(jj & 1) * 2 + 1]);
        }
        cs++; if (cs >= 3) cs = 0;
    }

    if (EPI == 0) {
        float* C = z ? a.C1 : a.C0;
#pragma unroll
        for (int ii = 0; ii < 2; ii++) {
            const int gr = bm + m0w + ii * 16 + (lane >> 2);
            const int r0 = flip ? (1023 - gr) : gr;
            const int r1 = flip ? (1023 - (gr + 8)) : (gr + 8);
#pragma unroll
            for (int jj = 0; jj < 4; jj++) {
                const int gc = bn + n0w + jj * 8 + (lane & 3) * 2;
                if (gc < N) {
                    *reinterpret_cast<float2*>(&C[(size_t)r0 * N + gc]) = make_float2(acc[ii][jj][0], acc[ii][jj][1]);
                    *reinterpret_cast<float2*>(&C[(size_t)r1 * N + gc]) = make_float2(acc[ii][jj][2], acc[ii][jj][3]);
                }
            }
        }
    } else {
        const int colOff = z * 1024;
#pragma unroll
        for (int ii = 0; ii < 2; ii++) {
            const int gr = bm + m0w + ii * 16 + (lane >> 2);
            const int r0 = flip ? (1023 - gr) : gr;
            const int r1 = flip ? (1023 - (gr + 8)) : (gr + 8);
#pragma unroll
            for (int jj = 0; jj < 4; jj++) {
                const int gc = colOff + bn + n0w + jj * 8 + (lane & 3) * 2;
                const float v0 = siluf(acc[ii][jj][0]);
                const float v1 = siluf(acc[ii][jj][1]);
                const float v2 = siluf(acc[ii][jj][2]);
                const float v3 = siluf(acc[ii][jj][3]);
                *reinterpret_cast<uint32_t*>(&a.E[(size_t)r0 * 2048 + gc]) = pack_h2(__float2half(v0), __float2half(v1));
                *reinterpret_cast<uint32_t*>(&a.E[(size_t)r1 * 2048 + gc]) = pack_h2(__float2half(v2), __float2half(v3));
            }
        }
    }
}

// ---------------- f32 -> f16 convert (+ zero pad rows), z-batched pair ----------------
__global__ void cvt_kernel(const float* __restrict__ s0, const float* __restrict__ s1,
                           __half* __restrict__ d0, __half* __restrict__ d1,
                           int rows, int K)
{
    const float* s = blockIdx.z ? s1 : s0;
    __half* d = blockIdx.z ? d1 : d0;
    const int r = blockIdx.y;
    const int c = (blockIdx.x * 256 + threadIdx.x) * 4;
    if (c >= K) return;
    float4 v = make_float4(0.f, 0.f, 0.f, 0.f);
    if (r < rows) v = *reinterpret_cast<const float4*>(&s[(size_t)r * K + c]);
    *reinterpret_cast<uint2*>(&d[(size_t)r * K + c]) =
        make_uint2(pack_h2(__float2half(v.x), __float2half(v.y)),
                   pack_h2(__float2half(v.z), __float2half(v.w)));
}

// ---------------- depthwise causal conv (width 4) + SiLU, z-batched ----------------
__global__ void conv_silu_kernel(const float* __restrict__ zx0, const float* __restrict__ zx1,
                                 const float* __restrict__ cw0, const float* __restrict__ cw1,
                                 const float* __restrict__ cb0, const float* __restrict__ cb1,
                                 float* __restrict__ out0, float* __restrict__ out1)
{
    const int z = blockIdx.y;
    const float* zx = z ? zx1 : zx0;
    const float* cw = z ? cw1 : cw0;
    const float* cb = z ? cb1 : cb0;
    float* out = z ? out1 : out0;
    const int idx = blockIdx.x * blockDim.x + threadIdx.x;
    if (idx >= L * CONVDIM) return;
    const int t = idx / CONVDIM;
    const int c = idx - t * CONVDIM;
    float acc = cb[c];
#pragma unroll
    for (int k = 0; k < 4; k++) {
        const int tt = t - 3 + k;
        if (tt >= 0)
            acc = fmaf(zx[(size_t)tt * DINPROJ + OFF_XBC + c], cw[c * 4 + k], acc);
    }
    out[(size_t)t * CONVDIM + c] = siluf(acc);
}

// ---------------- dt softplus + dA, z-batched ----------------
__global__ void dt_kernel(const float* __restrict__ zx0, const float* __restrict__ zx1,
                          const float* __restrict__ db0, const float* __restrict__ db1,
                          const float* __restrict__ al0, const float* __restrict__ al1,
                          float* __restrict__ dt0, float* __restrict__ dt1,
                          float* __restrict__ dA0, float* __restrict__ dA1)
{
    const int z = blockIdx.y;
    const float* zx = z ? zx1 : zx0;
    const float* dt_bias = z ? db1 : db0;
    const float* A_log = z ? al1 : al0;
    float* dt_out = z ? dt1 : dt0;
    float* dA_out = z ? dA1 : dA0;
    const int idx = blockIdx.x * blockDim.x + threadIdx.x;
    if (idx >= L * NH) return;
    const int h = idx & (NH - 1);
    const float v = zx[(size_t)(idx >> 5) * DINPROJ + OFF_DT + h] + dt_bias[h];
    const float sp = (v > 20.f) ? v : log1pf(expf(v));
    dt_out[idx] = sp;
    dA_out[idx] = expf(sp * (-expf(A_log[h])));
}

// ---------------- SSM scan, z-batched ----------------
#define SCHUNK 16
__global__ void __launch_bounds__(256) scan_kernel(
    const float* __restrict__ xbc0, const float* __restrict__ xbc1,
    const float* __restrict__ dtp0, const float* __restrict__ dtp1,
    const float* __restrict__ dAp0, const float* __restrict__ dAp1,
    const float* __restrict__ Dp0, const float* __restrict__ Dp1,
    float* __restrict__ y0, float* __restrict__ y1)
{
    const int z = blockIdx.z;
    const float* xbc = z ? xbc1 : xbc0;
    const float* dt = z ? dtp1 : dtp0;
    const float* dA = z ? dAp1 : dAp0;
    const float* Dp = z ? Dp1 : Dp0;
    float* y = z ? y1 : y0;

    const int head = blockIdx.y;
    const int ps   = blockIdx.x;
    const int tid  = threadIdx.x;
    const int pl   = tid >> 3;
    const int n0   = (tid & 7) * 8;
    const float Dh = Dp[head];
    const int xoff = head * HD + ps * 32;

    __shared__ float sB[SCHUNK][64];
    __shared__ float sC[SCHUNK][64];
    __shared__ float sx[SCHUNK][32];
    __shared__ float sdt[SCHUNK];
    __shared__ float sdA[SCHUNK];

    float h[8];
#pragma unroll
    for (int j = 0; j < 8; j++) h[j] = 0.f;

    for (int t0 = 0; t0 < L; t0 += SCHUNK) {
        {
            const int lt = tid >> 4;
            const int lc = (tid & 15) * 4;
            const int t  = t0 + lt;
            *reinterpret_cast<float4*>(&sB[lt][lc]) =
                *reinterpret_cast<const float4*>(&xbc[(size_t)t * CONVDIM + OFF_B + lc]);
            *reinterpret_cast<float4*>(&sC[lt][lc]) =
                *reinterpret_cast<const float4*>(&xbc[(size_t)t * CONVDIM + OFF_B + 64 + lc]);
            if (lc < 32)
                *reinterpret_cast<float4*>(&sx[lt][lc]) =
                    *reinterpret_cast<const float4*>(&xbc[(size_t)t * CONVDIM + xoff + lc]);
            if (tid < SCHUNK) {
                sdt[tid] = dt[(size_t)(t0 + tid) * NH + head];
                sdA[tid] = dA[(size_t)(t0 + tid) * NH + head];
            }
        }
        __syncthreads();

        for (int tt = 0; tt < SCHUNK; tt++) {
            const float dtv = sdt[tt];
            const float dAv = sdA[tt];
            const float xp  = sx[tt][pl];
            const float dtx = dtv * xp;
            float b[8], c[8];
            *reinterpret_cast<float4*>(b)     = *reinterpret_cast<const float4*>(&sB[tt][n0]);
            *reinterpret_cast<float4*>(b + 4) = *reinterpret_cast<const float4*>(&sB[tt][n0 + 4]);
            *reinterpret_cast<float4*>(c)     = *reinterpret_cast<const float4*>(&sC[tt][n0]);
            *reinterpret_cast<float4*>(c + 4) = *reinterpret_cast<const float4*>(&sC[tt][n0 + 4]);
            float acc = 0.f;
#pragma unroll
            for (int j = 0; j < 8; j++) {
                h[j] = fmaf(h[j], dAv, dtx * b[j]);
                acc  = fmaf(h[j], c[j], acc);
            }
            acc += __shfl_down_sync(0xffffffffu, acc, 4, 8);
            acc += __shfl_down_sync(0xffffffffu, acc, 2, 8);
            acc += __shfl_down_sync(0xffffffffu, acc, 1, 8);
            if ((tid & 7) == 0)
                y[(size_t)(t0 + tt) * DINNER + head * HD + ps * 32 + pl] = fmaf(Dh, xp, acc);
        }
        __syncthreads();
    }
}

// ---------------- gate + RMSNorm -> f16, z-batched ----------------
__global__ void __launch_bounds__(256) gatenorm_kernel(
    const float* __restrict__ zx0, const float* __restrict__ zx1,
    const float* __restrict__ nw0, const float* __restrict__ nw1,
    const float* __restrict__ y0, const float* __restrict__ y1,
    __half* __restrict__ yh0, __half* __restrict__ yh1)
{
    const int z = blockIdx.y;
    const float* zx = z ? zx1 : zx0;
    const float* norm_w = z ? nw1 : nw0;
    const float* y = z ? y1 : y0;
    __half* yh = z ? yh1 : yh0;

    const int t = blockIdx.x;
    const int tid = threadIdx.x;
    __shared__ float red[8];

    float vals[8];
    float local = 0.f;
#pragma unroll
    for (int i = 0; i < 8; i++) {
        const int c = tid + i * 256;
        const float zz = zx[(size_t)t * DINPROJ + OFF_Z + c];
        const float yv = y[(size_t)t * DINNER + c];
        const float yg = yv * siluf(zz);
        vals[i] = yg;
        local = fmaf(yg, yg, local);
    }
#pragma unroll
    for (int o = 16; o > 0; o >>= 1)
        local += __shfl_down_sync(0xffffffffu, local, o);
    if ((tid & 31) == 0) red[tid >> 5] = local;
    __syncthreads();
    if (tid < 8) {
        float v = red[tid];
#pragma unroll
        for (int o = 4; o > 0; o >>= 1)
            v += __shfl_down_sync(0xffu, v, o, 8);
        if (tid == 0) red[0] = v;
    }
    __syncthreads();
    const float scale = rsqrtf(red[0] * (1.f / (float)DINNER) + EPSF);
#pragma unroll
    for (int i = 0; i < 8; i++) {
        const int c = tid + i * 256;
        yh[(size_t)t * DINNER + c] = __float2half(vals[i] * scale * norm_w[c]);
    }
}

// ---------------- launch ----------------
extern "C" void kernel_launch(void* const* d_in, const int* in_sizes, int n_in,
                              void* d_out, int out_size)
{
    const float* u        = (const float*)d_in[0];
    const float* W_in_f   = (const float*)d_in[1];
    const float* W_in_b   = (const float*)d_in[2];
    const float* conv_w_f = (const float*)d_in[3];
    const float* conv_b_f = (const float*)d_in[4];
    const float* conv_w_b = (const float*)d_in[5];
    const float* conv_b_b = (const float*)d_in[6];
    const float* dtb_f    = (const float*)d_in[7];
    const float* dtb_b    = (const float*)d_in[8];
    const float* Alog_f   = (const float*)d_in[9];
    const float* Alog_b   = (const float*)d_in[10];
    const float* D_f      = (const float*)d_in[11];
    const float* D_b      = (const float*)d_in[12];
    const float* nw_f     = (const float*)d_in[13];
    const float* nw_b     = (const float*)d_in[14];
    const float* W_out_f  = (const float*)d_in[15];
    const float* W_out_b  = (const float*)d_in[16];
    const float* W_out    = (const float*)d_in[17];
    float* out = (float*)d_out;

    float *zx_f, *zx_b, *xbc_f, *xbc_b, *dt_f, *dt_b, *dA_f, *dA_b, *y_f, *y_b;
    cudaGetSymbolAddress((void**)&zx_f,  g_zx_f);
    cudaGetSymbolAddress((void**)&zx_b,  g_zx_b);
    cudaGetSymbolAddress((void**)&xbc_f, g_xbc_f);
    cudaGetSymbolAddress((void**)&xbc_b, g_xbc_b);
    cudaGetSymbolAddress((void**)&dt_f,  g_dt_f);
    cudaGetSymbolAddress((void**)&dt_b,  g_dt_b);
    cudaGetSymbolAddress((void**)&dA_f,  g_dA_f);
    cudaGetSymbolAddress((void**)&dA_b,  g_dA_b);
    cudaGetSymbolAddress((void**)&y_f,   g_y_f);
    cudaGetSymbolAddress((void**)&y_b,   g_y_b);

    __half *u16, *win16_f, *win16_b, *wout16_f, *wout16_b, *wfin16, *y16_f, *y16_b, *f16;
    cudaGetSymbolAddress((void**)&u16,      g_u16);
    cudaGetSymbolAddress((void**)&win16_f,  g_win16_f);
    cudaGetSymbolAddress((void**)&win16_b,  g_win16_b);
    cudaGetSymbolAddress((void**)&wout16_f, g_wout16_f);
    cudaGetSymbolAddress((void**)&wout16_b, g_wout16_b);
    cudaGetSymbolAddress((void**)&wfin16,   g_wfin16);
    cudaGetSymbolAddress((void**)&y16_f,    g_y16_f);
    cudaGetSymbolAddress((void**)&y16_b,    g_y16_b);
    cudaGetSymbolAddress((void**)&f16,      g_f16);

    constexpr int SMEM_128 = 3 * 16384;
    constexpr int SMEM_64  = 3 * 12288;
    cudaFuncSetAttribute(gemm128,   cudaFuncAttributeMaxDynamicSharedMemorySize, SMEM_128);
    cudaFuncSetAttribute(gemm64<0>, cudaFuncAttributeMaxDynamicSharedMemorySize, SMEM_64);
    cudaFuncSetAttribute(gemm64<1>, cudaFuncAttributeMaxDynamicSharedMemorySize, SMEM_64);

    // idx0: u convert
    cvt_kernel<<<dim3(1, L, 1), 256>>>(u, u, u16, u16, L, DMODEL);
    // idx1: in_proj weight converts (f+b batched)
    cvt_kernel<<<dim3(1, DINPROJ_PAD, 2), 256>>>(W_in_f, W_in_b, win16_f, win16_b, DINPROJ, DMODEL);

    // idx2 / idx3 (ncu capture slots): in_proj GEMMs, one launch per direction
    {
        GArgs ga = {};
        ga.A0 = u16; ga.W0 = win16_f; ga.C0 = zx_f;
        ga.N = DINPROJ; ga.K = DMODEL; ga.flip0 = 0;
        dim3 grid(DINPROJ_PAD / 128, 8, 1);
        gemm128<<<grid, 512, SMEM_128>>>(ga);
        GArgs gb = {};
        gb.A0 = u16; gb.W0 = win16_b; gb.C0 = zx_b;
        gb.N = DINPROJ; gb.K = DMODEL; gb.flip0 = 1;
        gemm128<<<grid, 512, SMEM_128>>>(gb);
    }
    // idx4: out_proj weight converts (f+b)
    cvt_kernel<<<dim3(2, DMODEL, 2), 256>>>(W_out_f, W_out_b, wout16_f, wout16_b, DMODEL, DINNER);
    // idx5: final weight convert
    cvt_kernel<<<dim3(2, DMODEL, 1), 256>>>(W_out, W_out, wfin16, wfin16, DMODEL, 2 * DMODEL);
    // idx6: conv + silu (f+b)
    conv_silu_kernel<<<dim3((L * CONVDIM + 255) / 256, 2), 256>>>(
        zx_f, zx_b, conv_w_f, conv_w_b, conv_b_f, conv_b_b, xbc_f, xbc_b);
    // idx7: dt / dA (f+b)
    dt_kernel<<<dim3((L * NH + 255) / 256, 2), 256>>>(
        zx_f, zx_b, dtb_f, dtb_b, Alog_f, Alog_b, dt_f, dt_b, dA_f, dA_b);
    // idx8: scan (f+b)
    scan_kernel<<<dim3(2, NH, 2), 256>>>(
        xbc_f, xbc_b, dt_f, dt_b, dA_f, dA_b, D_f, D_b, y_f, y_b);
    // idx9: gate + rmsnorm -> f16 (f+b)
    gatenorm_kernel<<<dim3(L, 2), 256>>>(
        zx_f, zx_b, nw_f, nw_b, y_f, y_b, y16_f, y16_b);
    // idx10: out_proj GEMM (f+b batched, fused silu -> f16 concat epilogue)
    {
        GArgs ga = {};
        ga.A0 = y16_f; ga.A1 = y16_b;
        ga.W0 = wout16_f; ga.W1 = wout16_b;
        ga.E = f16;
        ga.N = DMODEL; ga.K = DINNER; ga.flip0 = 0; ga.flip1 = 1;
        dim3 grid(DMODEL / 64, 8, 2);
        gemm64<1><<<grid, 256, SMEM_64>>>(ga);
    }
    // idx11: final GEMM: f16concat @ W_out^T -> out
    {
        GArgs ga = {};
        ga.A0 = f16; ga.W0 = wfin16; ga.C0 = out;
        ga.N = DMODEL; ga.K = 2 * DMODEL; ga.flip0 = 0;
        dim3 grid(DMODEL / 64, 8, 1);
        gemm64<0><<<grid, 256, SMEM_64>>>(ga);
    }
}

// round 9
// speedup vs baseline: 2.2132x; 1.0685x over previous
#include <cuda_runtime.h>
#include <cuda_fp16.h>
#include <math.h>
#include <stdint.h>

// ---------------- problem constants ----------------
#define L        1024
#define DMODEL   1024
#define DINNER   2048
#define NH       32
#define HD       64
#define CONVDIM  2176           // DINNER + 2*G*N
#define DINPROJ  4256           // 2*DINNER + 2*G*N + NH
#define DINPROJ_PAD 4352        // 34 * 128
#define OFF_Z    0
#define OFF_XBC  2048
#define OFF_B    2048
#define OFF_DT   4224
#define EPSF     1e-5f

// ---------------- scratch (device globals; no allocs allowed) ----------------
__device__ float g_zx_f[L * DINPROJ];
__device__ float g_zx_b[L * DINPROJ];
__device__ float g_xbc_f[L * CONVDIM];
__device__ float g_xbc_b[L * CONVDIM];
__device__ float g_dt_f[L * NH];
__device__ float g_dt_b[L * NH];
__device__ float g_dA_f[L * NH];
__device__ float g_dA_b[L * NH];
__device__ float g_y_f[L * DINNER];
__device__ float g_y_b[L * DINNER];

// fp16 operands
__device__ __half g_u16[L * DMODEL];
__device__ __half g_win16_f[DINPROJ_PAD * DMODEL];
__device__ __half g_win16_b[DINPROJ_PAD * DMODEL];
__device__ __half g_wout16_f[DMODEL * DINNER];
__device__ __half g_wout16_b[DMODEL * DINNER];
__device__ __half g_wfin16[DMODEL * (2 * DMODEL)];
__device__ __half g_y16_f[L * DINNER];
__device__ __half g_y16_b[L * DINNER];
__device__ __half g_f16[L * (2 * DMODEL)];

__device__ __forceinline__ float siluf(float x) { return x / (1.f + expf(-x)); }

// ---------------- PTX helpers ----------------
__device__ __forceinline__ uint32_t smem_u32(const void* p) {
    uint32_t a;
    asm("{ .reg .u64 t; cvta.to.shared.u64 t, %1; cvt.u32.u64 %0, t; }" : "=r"(a) : "l"(p));
    return a;
}
__device__ __forceinline__ void cpa16(uint32_t dst, const void* src) {
    asm volatile("cp.async.cg.shared.global [%0], [%1], 16;" :: "r"(dst), "l"(src));
}
#define CP_COMMIT asm volatile("cp.async.commit_group;" ::: "memory")
#define CP_WAIT(n) asm volatile("cp.async.wait_group %0;" :: "n"(n) : "memory")

__device__ __forceinline__ void ldm_x4(uint32_t a[4], uint32_t addr) {
    asm volatile("ldmatrix.sync.aligned.m8n8.x4.shared.b16 {%0,%1,%2,%3}, [%4];"
        : "=r"(a[0]), "=r"(a[1]), "=r"(a[2]), "=r"(a[3]) : "r"(addr));
}
__device__ __forceinline__ void mma_f16(float c[4], const uint32_t a[4], uint32_t b0, uint32_t b1) {
    asm volatile("mma.sync.aligned.m16n8k16.row.col.f32.f16.f16.f32 "
        "{%0,%1,%2,%3}, {%4,%5,%6,%7}, {%8,%9}, {%0,%1,%2,%3};"
        : "+f"(c[0]), "+f"(c[1]), "+f"(c[2]), "+f"(c[3])
        : "r"(a[0]), "r"(a[1]), "r"(a[2]), "r"(a[3]), "r"(b0), "r"(b1));
}
__device__ __forceinline__ uint32_t pack_h2(__half a, __half b) {
    __half2 t(a, b);
    return *reinterpret_cast<uint32_t*>(&t);
}

// ---------------- GEMM argument bundle ----------------
struct GArgs {
    const __half *A0, *A1, *W0, *W1;
    float *C0, *C1;        // EPI=0
    __half *E;             // EPI=1 (silu -> f16 concat buffer, row stride 2048)
    int N, K;
    int flip0, flip1;      // epilogue row flips per z
};

// ================= Unified GEMM: BM=128, BK=64, 256 threads / 8 warps =================
// BN=128: warp tile 32x64 (4x2 warp grid). BN=64: warp tile 32x32.
// fp16 single-term, fp32 acc. 3-stage cp.async, one __syncthreads per BK=64 chunk.
// Smem rows are 128B (64 f16); 16B chunk swizzle: ch ^= (row & 7).
// EPI 0: fp32 store (row-flip per z). EPI 1: silu -> f16 concat store (colOff z*1024).
template <int BN, int EPI>
__global__ void __launch_bounds__(256) gemm_k(GArgs a)
{
    constexpr int WN = BN / 2;            // warp N-extent: 64 or 32
    constexpr int NT = WN / 8;            // n8 tiles per warp: 8 or 4
    constexpr int NG = WN / 16;           // ldm groups per ks: 4 or 2
    constexpr int STAGE = 16384 + BN * 128;
    extern __shared__ __align__(128) char smem[];
    const uint32_t sb = smem_u32(smem);
    const int tid = threadIdx.x;
    const int lane = tid & 31;
    const int wid = tid >> 5;             // 0..7
    const int z = blockIdx.z;
    const int bm = blockIdx.y * 128;
    const int bn = blockIdx.x * BN;
    const int m0w = (wid >> 1) * 32;
    const int n0w = (wid & 1) * WN;
    const int N = a.N, K = a.K;

    const __half* A = z ? a.A1 : a.A0;
    const __half* W = z ? a.W1 : a.W0;
    const bool flip = z ? (a.flip1 != 0) : (a.flip0 != 0);

    float acc[2][NT][4];
#pragma unroll
    for (int i = 0; i < 2; i++)
#pragma unroll
        for (int j = 0; j < NT; j++)
#pragma unroll
            for (int q = 0; q < 4; q++) acc[i][j][q] = 0.f;

    auto load_stage = [&](int s, int k0) {
        const uint32_t base = sb + s * STAGE;
        // A: 128 rows x 8 chunks (16B) = 1024 chunks, 4 iters
#pragma unroll
        for (int it = 0; it < 4; it++) {
            const int q = tid + it * 256;
            const int r = q >> 3, c = q & 7;
            const uint32_t sw = r * 128 + ((uint32_t)(c ^ (r & 7)) << 4);
            cpa16(base + sw, A + (size_t)(bm + r) * K + k0 + c * 8);
        }
        // W: BN rows x 8 chunks
#pragma unroll
        for (int it = 0; it < BN / 32; it++) {
            const int q = tid + it * 256;
            const int r = q >> 3, c = q & 7;
            const uint32_t sw = r * 128 + ((uint32_t)(c ^ (r & 7)) << 4);
            cpa16(base + 16384 + sw, W + (size_t)(bn + r) * K + k0 + c * 8);
        }
    };

    const int NC = K >> 6;
    load_stage(0, 0);
    CP_COMMIT;
    load_stage(1, 64);
    CP_COMMIT;

    int cs = 0;
    for (int i = 0; i < NC; i++) {
        if (i + 1 < NC) { CP_WAIT(1); } else { CP_WAIT(0); }
        __syncthreads();
        if (i + 2 < NC) {
            int ps = cs + 2; if (ps >= 3) ps -= 3;
            load_stage(ps, (i + 2) << 6);
            CP_COMMIT;
        }
        const uint32_t base = sb + cs * STAGE;
#pragma unroll
        for (int ks = 0; ks < 4; ks++) {
            const int c0 = ks * 2;            // 16B chunk pair = k16
            uint32_t af[2][4], bw[NG][4];
#pragma unroll
            for (int ii = 0; ii < 2; ii++) {
                const int row = m0w + ii * 16 + (lane & 15);
                const int ch = c0 + (lane >> 4);
                ldm_x4(af[ii], base + row * 128 + (uint32_t)((ch ^ (row & 7)) << 4));
            }
#pragma unroll
            for (int j = 0; j < NG; j++) {
                const int row = n0w + j * 16 + ((lane >> 4) << 3) + (lane & 7);
                const int ch = c0 + ((lane >> 3) & 1);
                ldm_x4(bw[j], base + 16384 + row * 128 + (uint32_t)((ch ^ (row & 7)) << 4));
            }
#pragma unroll
            for (int ii = 0; ii < 2; ii++)
#pragma unroll
                for (int jj = 0; jj < NT; jj++)
                    mma_f16(acc[ii][jj], af[ii], bw[jj >> 1][(jj & 1) * 2], bw[jj >> 1][(jj & 1) * 2 + 1]);
        }
        cs++; if (cs >= 3) cs = 0;
    }

    if (EPI == 0) {
        float* C = z ? a.C1 : a.C0;
#pragma unroll
        for (int ii = 0; ii < 2; ii++) {
            const int gr = bm + m0w + ii * 16 + (lane >> 2);
            const int r0 = flip ? (1023 - gr) : gr;
            const int r1 = flip ? (1023 - (gr + 8)) : (gr + 8);
#pragma unroll
            for (int jj = 0; jj < NT; jj++) {
                const int gc = bn + n0w + jj * 8 + (lane & 3) * 2;
                if (gc < N) {
                    *reinterpret_cast<float2*>(&C[(size_t)r0 * N + gc]) = make_float2(acc[ii][jj][0], acc[ii][jj][1]);
                    *reinterpret_cast<float2*>(&C[(size_t)r1 * N + gc]) = make_float2(acc[ii][jj][2], acc[ii][jj][3]);
                }
            }
        }
    } else {
        const int colOff = z * 1024;
#pragma unroll
        for (int ii = 0; ii < 2; ii++) {
            const int gr = bm + m0w + ii * 16 + (lane >> 2);
            const int r0 = flip ? (1023 - gr) : gr;
            const int r1 = flip ? (1023 - (gr + 8)) : (gr + 8);
#pragma unroll
            for (int jj = 0; jj < NT; jj++) {
                const int gc = colOff + bn + n0w + jj * 8 + (lane & 3) * 2;
                const float v0 = siluf(acc[ii][jj][0]);
                const float v1 = siluf(acc[ii][jj][1]);
                const float v2 = siluf(acc[ii][jj][2]);
                const float v3 = siluf(acc[ii][jj][3]);
                *reinterpret_cast<uint32_t*>(&a.E[(size_t)r0 * 2048 + gc]) = pack_h2(__float2half(v0), __float2half(v1));
                *reinterpret_cast<uint32_t*>(&a.E[(size_t)r1 * 2048 + gc]) = pack_h2(__float2half(v2), __float2half(v3));
            }
        }
    }
}

// ---------------- f32 -> f16 convert (+ zero pad rows), z-batched pair ----------------
__global__ void cvt_kernel(const float* __restrict__ s0, const float* __restrict__ s1,
                           __half* __restrict__ d0, __half* __restrict__ d1,
                           int rows, int K)
{
    const float* s = blockIdx.z ? s1 : s0;
    __half* d = blockIdx.z ? d1 : d0;
    const int r = blockIdx.y;
    const int c = (blockIdx.x * 256 + threadIdx.x) * 4;
    if (c >= K) return;
    float4 v = make_float4(0.f, 0.f, 0.f, 0.f);
    if (r < rows) v = *reinterpret_cast<const float4*>(&s[(size_t)r * K + c]);
    *reinterpret_cast<uint2*>(&d[(size_t)r * K + c]) =
        make_uint2(pack_h2(__float2half(v.x), __float2half(v.y)),
                   pack_h2(__float2half(v.z), __float2half(v.w)));
}

// ---------------- depthwise causal conv (width 4) + SiLU, z-batched ----------------
__global__ void conv_silu_kernel(const float* __restrict__ zx0, const float* __restrict__ zx1,
                                 const float* __restrict__ cw0, const float* __restrict__ cw1,
                                 const float* __restrict__ cb0, const float* __restrict__ cb1,
                                 float* __restrict__ out0, float* __restrict__ out1)
{
    const int z = blockIdx.y;
    const float* zx = z ? zx1 : zx0;
    const float* cw = z ? cw1 : cw0;
    const float* cb = z ? cb1 : cb0;
    float* out = z ? out1 : out0;
    const int idx = blockIdx.x * blockDim.x + threadIdx.x;
    if (idx >= L * CONVDIM) return;
    const int t = idx / CONVDIM;
    const int c = idx - t * CONVDIM;
    float acc = cb[c];
#pragma unroll
    for (int k = 0; k < 4; k++) {
        const int tt = t - 3 + k;
        if (tt >= 0)
            acc = fmaf(zx[(size_t)tt * DINPROJ + OFF_XBC + c], cw[c * 4 + k], acc);
    }
    out[(size_t)t * CONVDIM + c] = siluf(acc);
}

// ---------------- dt softplus + dA, z-batched ----------------
__global__ void dt_kernel(const float* __restrict__ zx0, const float* __restrict__ zx1,
                          const float* __restrict__ db0, const float* __restrict__ db1,
                          const float* __restrict__ al0, const float* __restrict__ al1,
                          float* __restrict__ dt0, float* __restrict__ dt1,
                          float* __restrict__ dA0, float* __restrict__ dA1)
{
    const int z = blockIdx.y;
    const float* zx = z ? zx1 : zx0;
    const float* dt_bias = z ? db1 : db0;
    const float* A_log = z ? al1 : al0;
    float* dt_out = z ? dt1 : dt0;
    float* dA_out = z ? dA1 : dA0;
    const int idx = blockIdx.x * blockDim.x + threadIdx.x;
    if (idx >= L * NH) return;
    const int h = idx & (NH - 1);
    const float v = zx[(size_t)(idx >> 5) * DINPROJ + OFF_DT + h] + dt_bias[h];
    const float sp = (v > 20.f) ? v : log1pf(expf(v));
    dt_out[idx] = sp;
    dA_out[idx] = expf(sp * (-expf(A_log[h])));
}

// ---------------- SSM scan, z-batched ----------------
#define SCHUNK 16
__global__ void __launch_bounds__(256) scan_kernel(
    const float* __restrict__ xbc0, const float* __restrict__ xbc1,
    const float* __restrict__ dtp0, const float* __restrict__ dtp1,
    const float* __restrict__ dAp0, const float* __restrict__ dAp1,
    const float* __restrict__ Dp0, const float* __restrict__ Dp1,
    float* __restrict__ y0, float* __restrict__ y1)
{
    const int z = blockIdx.z;
    const float* xbc = z ? xbc1 : xbc0;
    const float* dt = z ? dtp1 : dtp0;
    const float* dA = z ? dAp1 : dAp0;
    const float* Dp = z ? Dp1 : Dp0;
    float* y = z ? y1 : y0;

    const int head = blockIdx.y;
    const int ps   = blockIdx.x;
    const int tid  = threadIdx.x;
    const int pl   = tid >> 3;
    const int n0   = (tid & 7) * 8;
    const float Dh = Dp[head];
    const int xoff = head * HD + ps * 32;

    __shared__ float sB[SCHUNK][64];
    __shared__ float sC[SCHUNK][64];
    __shared__ float sx[SCHUNK][32];
    __shared__ float sdt[SCHUNK];
    __shared__ float sdA[SCHUNK];

    float h[8];
#pragma unroll
    for (int j = 0; j < 8; j++) h[j] = 0.f;

    for (int t0 = 0; t0 < L; t0 += SCHUNK) {
        {
            const int lt = tid >> 4;
            const int lc = (tid & 15) * 4;
            const int t  = t0 + lt;
            *reinterpret_cast<float4*>(&sB[lt][lc]) =
                *reinterpret_cast<const float4*>(&xbc[(size_t)t * CONVDIM + OFF_B + lc]);
            *reinterpret_cast<float4*>(&sC[lt][lc]) =
                *reinterpret_cast<const float4*>(&xbc[(size_t)t * CONVDIM + OFF_B + 64 + lc]);
            if (lc < 32)
                *reinterpret_cast<float4*>(&sx[lt][lc]) =
                    *reinterpret_cast<const float4*>(&xbc[(size_t)t * CONVDIM + xoff + lc]);
            if (tid < SCHUNK) {
                sdt[tid] = dt[(size_t)(t0 + tid) * NH + head];
                sdA[tid] = dA[(size_t)(t0 + tid) * NH + head];
            }
        }
        __syncthreads();

        for (int tt = 0; tt < SCHUNK; tt++) {
            const float dtv = sdt[tt];
            const float dAv = sdA[tt];
            const float xp  = sx[tt][pl];
            const float dtx = dtv * xp;
            float b[8], c[8];
            *reinterpret_cast<float4*>(b)     = *reinterpret_cast<const float4*>(&sB[tt][n0]);
            *reinterpret_cast<float4*>(b + 4) = *reinterpret_cast<const float4*>(&sB[tt][n0 + 4]);
            *reinterpret_cast<float4*>(c)     = *reinterpret_cast<const float4*>(&sC[tt][n0]);
            *reinterpret_cast<float4*>(c + 4) = *reinterpret_cast<const float4*>(&sC[tt][n0 + 4]);
            float acc = 0.f;
#pragma unroll
            for (int j = 0; j < 8; j++) {
                h[j] = fmaf(h[j], dAv, dtx * b[j]);
                acc  = fmaf(h[j], c[j], acc);
            }
            acc += __shfl_down_sync(0xffffffffu, acc, 4, 8);
            acc += __shfl_down_sync(0xffffffffu, acc, 2, 8);
            acc += __shfl_down_sync(0xffffffffu, acc, 1, 8);
            if ((tid & 7) == 0)
                y[(size_t)(t0 + tt) * DINNER + head * HD + ps * 32 + pl] = fmaf(Dh, xp, acc);
        }
        __syncthreads();
    }
}

// ---------------- gate + RMSNorm -> f16, z-batched ----------------
__global__ void __launch_bounds__(256) gatenorm_kernel(
    const float* __restrict__ zx0, const float* __restrict__ zx1,
    const float* __restrict__ nw0, const float* __restrict__ nw1,
    const float* __restrict__ y0, const float* __restrict__ y1,
    __half* __restrict__ yh0, __half* __restrict__ yh1)
{
    const int z = blockIdx.y;
    const float* zx = z ? zx1 : zx0;
    const float* norm_w = z ? nw1 : nw0;
    const float* y = z ? y1 : y0;
    __half* yh = z ? yh1 : yh0;

    const int t = blockIdx.x;
    const int tid = threadIdx.x;
    __shared__ float red[8];

    float vals[8];
    float local = 0.f;
#pragma unroll
    for (int i = 0; i < 8; i++) {
        const int c = tid + i * 256;
        const float zz = zx[(size_t)t * DINPROJ + OFF_Z + c];
        const float yv = y[(size_t)t * DINNER + c];
        const float yg = yv * siluf(zz);
        vals[i] = yg;
        local = fmaf(yg, yg, local);
    }
#pragma unroll
    for (int o = 16; o > 0; o >>= 1)
        local += __shfl_down_sync(0xffffffffu, local, o);
    if ((tid & 31) == 0) red[tid >> 5] = local;
    __syncthreads();
    if (tid < 8) {
        float v = red[tid];
#pragma unroll
        for (int o = 4; o > 0; o >>= 1)
            v += __shfl_down_sync(0xffu, v, o, 8);
        if (tid == 0) red[0] = v;
    }
    __syncthreads();
    const float scale = rsqrtf(red[0] * (1.f / (float)DINNER) + EPSF);
#pragma unroll
    for (int i = 0; i < 8; i++) {
        const int c = tid + i * 256;
        yh[(size_t)t * DINNER + c] = __float2half(vals[i] * scale * norm_w[c]);
    }
}

// ---------------- launch ----------------
extern "C" void kernel_launch(void* const* d_in, const int* in_sizes, int n_in,
                              void* d_out, int out_size)
{
    const float* u        = (const float*)d_in[0];
    const float* W_in_f   = (const float*)d_in[1];
    const float* W_in_b   = (const float*)d_in[2];
    const float* conv_w_f = (const float*)d_in[3];
    const float* conv_b_f = (const float*)d_in[4];
    const float* conv_w_b = (const float*)d_in[5];
    const float* conv_b_b = (const float*)d_in[6];
    const float* dtb_f    = (const float*)d_in[7];
    const float* dtb_b    = (const float*)d_in[8];
    const float* Alog_f   = (const float*)d_in[9];
    const float* Alog_b   = (const float*)d_in[10];
    const float* D_f      = (const float*)d_in[11];
    const float* D_b      = (const float*)d_in[12];
    const float* nw_f     = (const float*)d_in[13];
    const float* nw_b     = (const float*)d_in[14];
    const float* W_out_f  = (const float*)d_in[15];
    const float* W_out_b  = (const float*)d_in[16];
    const float* W_out    = (const float*)d_in[17];
    float* out = (float*)d_out;

    float *zx_f, *zx_b, *xbc_f, *xbc_b, *dt_f, *dt_b, *dA_f, *dA_b, *y_f, *y_b;
    cudaGetSymbolAddress((void**)&zx_f,  g_zx_f);
    cudaGetSymbolAddress((void**)&zx_b,  g_zx_b);
    cudaGetSymbolAddress((void**)&xbc_f, g_xbc_f);
    cudaGetSymbolAddress((void**)&xbc_b, g_xbc_b);
    cudaGetSymbolAddress((void**)&dt_f,  g_dt_f);
    cudaGetSymbolAddress((void**)&dt_b,  g_dt_b);
    cudaGetSymbolAddress((void**)&dA_f,  g_dA_f);
    cudaGetSymbolAddress((void**)&dA_b,  g_dA_b);
    cudaGetSymbolAddress((void**)&y_f,   g_y_f);
    cudaGetSymbolAddress((void**)&y_b,   g_y_b);

    __half *u16, *win16_f, *win16_b, *wout16_f, *wout16_b, *wfin16, *y16_f, *y16_b, *f16;
    cudaGetSymbolAddress((void**)&u16,      g_u16);
    cudaGetSymbolAddress((void**)&win16_f,  g_win16_f);
    cudaGetSymbolAddress((void**)&win16_b,  g_win16_b);
    cudaGetSymbolAddress((void**)&wout16_f, g_wout16_f);
    cudaGetSymbolAddress((void**)&wout16_b, g_wout16_b);
    cudaGetSymbolAddress((void**)&wfin16,   g_wfin16);
    cudaGetSymbolAddress((void**)&y16_f,    g_y16_f);
    cudaGetSymbolAddress((void**)&y16_b,    g_y16_b);
    cudaGetSymbolAddress((void**)&f16,      g_f16);

    constexpr int SMEM_128 = 3 * (16384 + 128 * 128);   // 98304
    constexpr int SMEM_64  = 3 * (16384 + 64 * 128);    // 73728
    cudaFuncSetAttribute(gemm_k<128, 0>, cudaFuncAttributeMaxDynamicSharedMemorySize, SMEM_128);
    cudaFuncSetAttribute(gemm_k<64, 0>,  cudaFuncAttributeMaxDynamicSharedMemorySize, SMEM_64);
    cudaFuncSetAttribute(gemm_k<64, 1>,  cudaFuncAttributeMaxDynamicSharedMemorySize, SMEM_64);

    // idx0: u convert
    cvt_kernel<<<dim3(1, L, 1), 256>>>(u, u, u16, u16, L, DMODEL);
    // idx1: in_proj weight converts (f+b batched)
    cvt_kernel<<<dim3(1, DINPROJ_PAD, 2), 256>>>(W_in_f, W_in_b, win16_f, win16_b, DINPROJ, DMODEL);

    // idx2 (ncu capture slot): in_proj GEMM, f+b batched (dir-b rows flipped)
    {
        GArgs ga = {};
        ga.A0 = u16; ga.A1 = u16;
        ga.W0 = win16_f; ga.W1 = win16_b;
        ga.C0 = zx_f; ga.C1 = zx_b;
        ga.N = DINPROJ; ga.K = DMODEL; ga.flip0 = 0; ga.flip1 = 1;
        dim3 grid(DINPROJ_PAD / 128, 8, 2);
        gemm_k<128, 0><<<grid, 256, SMEM_128>>>(ga);
    }
    // idx3: out_proj weight converts (f+b)
    cvt_kernel<<<dim3(2, DMODEL, 2), 256>>>(W_out_f, W_out_b, wout16_f, wout16_b, DMODEL, DINNER);
    // idx4: final weight convert
    cvt_kernel<<<dim3(2, DMODEL, 1), 256>>>(W_out, W_out, wfin16, wfin16, DMODEL, 2 * DMODEL);
    // idx5: conv + silu (f+b)
    conv_silu_kernel<<<dim3((L * CONVDIM + 255) / 256, 2), 256>>>(
        zx_f, zx_b, conv_w_f, conv_w_b, conv_b_f, conv_b_b, xbc_f, xbc_b);
    // idx6: dt / dA (f+b)
    dt_kernel<<<dim3((L * NH + 255) / 256, 2), 256>>>(
        zx_f, zx_b, dtb_f, dtb_b, Alog_f, Alog_b, dt_f, dt_b, dA_f, dA_b);
    // idx7: scan (f+b)
    scan_kernel<<<dim3(2, NH, 2), 256>>>(
        xbc_f, xbc_b, dt_f, dt_b, dA_f, dA_b, D_f, D_b, y_f, y_b);
    // idx8: gate + rmsnorm -> f16 (f+b)
    gatenorm_kernel<<<dim3(L, 2), 256>>>(
        zx_f, zx_b, nw_f, nw_b, y_f, y_b, y16_f, y16_b);
    // idx9: out_proj GEMM (f+b batched, fused silu -> f16 concat epilogue)
    {
        GArgs ga = {};
        ga.A0 = y16_f; ga.A1 = y16_b;
        ga.W0 = wout16_f; ga.W1 = wout16_b;
        ga.E = f16;
        ga.N = DMODEL; ga.K = DINNER; ga.flip0 = 0; ga.flip1 = 1;
        dim3 grid(DMODEL / 64, 8, 2);
        gemm_k<64, 1><<<grid, 256, SMEM_64>>>(ga);
    }
    // idx10: final GEMM: f16concat @ W_out^T -> out
    {
        GArgs ga = {};
        ga.A0 = f16; ga.W0 = wfin16; ga.C0 = out;
        ga.N = DMODEL; ga.K = 2 * DMODEL; ga.flip0 = 0;
        dim3 grid(DMODEL / 64, 8, 1);
        gemm_k<64, 0><<<grid, 256, SMEM_64>>>(ga);
    }
}